// round 11
// baseline (speedup 1.0000x reference)
#include <cuda_runtime.h>
#include <cuda_bf16.h>
#include <cstdint>
#include <math.h>

#define BSZ 4096
#define FDIM 768
#define PDIM 500
#define ZDIM 300
#define RNUM 10
#define NRET (BSZ * RNUM)          // 40960
#define EDGE_ROWS (BSZ * 4)        // 16384
#define M_ROWS (EDGE_ROWS + RNUM)  // 16394
#define FEATD 2100
#define H1D 800
#define H2D 200

#define MROWS_P 16512              // 129*128
#define KP_HG 512
#define KP_P1 2112
#define KP_P2 800

// ---------------- fp32 scratch ----------------
__device__ float g_Rout[3ull * NRET * PDIM];
__device__ float g_E[3ull * BSZ * PDIM];
__device__ float g_Y[(size_t)M_ROWS * ZDIM];
__device__ float g_h2[(size_t)BSZ * H2D];
__device__ float g_bias[8192];
// [0..3072) 6x512 embed biases, [3072..3584) hg, [3584..4608) p1, [4608..4864) p2

// ---------------- bf16 hi/lo planes ----------------
__device__ __align__(16) __nv_bfloat16 g_aS[3ull * 2 * BSZ * FDIM];
__device__ __align__(16) __nv_bfloat16 g_aR[3ull * 2 * NRET * FDIM];
__device__ __align__(16) __nv_bfloat16 g_wE[6ull * 2 * 512 * FDIM];
__device__ __align__(16) __nv_bfloat16 g_aM[2ull * MROWS_P * KP_HG];
__device__ __align__(16) __nv_bfloat16 g_wHg[2ull * 512 * KP_HG];
__device__ __align__(16) __nv_bfloat16 g_aF[2ull * BSZ * KP_P1];
__device__ __align__(16) __nv_bfloat16 g_wP1[2ull * 1024 * KP_P1];
__device__ __align__(16) __nv_bfloat16 g_aH1[2ull * BSZ * KP_P2];
__device__ __align__(16) __nv_bfloat16 g_wP2[2ull * 256 * KP_P2];

// ---------------- helpers ----------------
__device__ __forceinline__ uint32_t smem_u32(const void* p) {
    uint32_t a;
    asm("{ .reg .u64 t; cvta.to.shared.u64 t, %1; cvt.u32.u64 %0, t; }" : "=r"(a) : "l"(p));
    return a;
}
__device__ __forceinline__ void ldsm4(uint32_t* r, uint32_t addr) {
    asm volatile("ldmatrix.sync.aligned.m8n8.x4.shared.b16 {%0,%1,%2,%3}, [%4];"
                 : "=r"(r[0]), "=r"(r[1]), "=r"(r[2]), "=r"(r[3]) : "r"(addr));
}
__device__ __forceinline__ void mma16816(float* d, const uint32_t* a, uint32_t b0, uint32_t b1) {
    asm volatile(
        "mma.sync.aligned.m16n8k16.row.col.f32.bf16.bf16.f32 "
        "{%0,%1,%2,%3}, {%4,%5,%6,%7}, {%8,%9}, {%0,%1,%2,%3};"
        : "+f"(d[0]), "+f"(d[1]), "+f"(d[2]), "+f"(d[3])
        : "r"(a[0]), "r"(a[1]), "r"(a[2]), "r"(a[3]), "r"(b0), "r"(b1));
}
__device__ __forceinline__ uint32_t swz(int row, int chunk) {
    return (uint32_t)(row * 64 + ((chunk ^ ((row >> 1) & 3)) << 4));
}
__device__ __forceinline__ void cpa16(uint32_t dst, const void* src) {
    asm volatile("cp.async.cg.shared.global [%0], [%1], 16;" :: "r"(dst), "l"(src));
}
__device__ __forceinline__ void cpa_commit() {
    asm volatile("cp.async.commit_group;" ::: "memory");
}
__device__ __forceinline__ void store_hl(__nv_bfloat16* hi, __nv_bfloat16* lo, float v) {
    const __nv_bfloat16 h = __float2bfloat16(v);
    *hi = h;
    *lo = __float2bfloat16(v - __bfloat162float(h));
}
__device__ __forceinline__ void pack4(const float* v, uint2& hi, uint2& lo) {
    __nv_bfloat16 h[4], l[4];
#pragma unroll
    for (int j = 0; j < 4; j++) {
        h[j] = __float2bfloat16(v[j]);
        l[j] = __float2bfloat16(v[j] - __bfloat162float(h[j]));
    }
    hi.x = ((uint32_t)*(uint16_t*)&h[1] << 16) | *(uint16_t*)&h[0];
    hi.y = ((uint32_t)*(uint16_t*)&h[3] << 16) | *(uint16_t*)&h[2];
    lo.x = ((uint32_t)*(uint16_t*)&l[1] << 16) | *(uint16_t*)&l[0];
    lo.y = ((uint32_t)*(uint16_t*)&l[3] << 16) | *(uint16_t*)&l[2];
}

#define STAGE_B 32768                 // Ahi8K Alo8K Whi8K Wlo8K
#define SMEM_BYTES (4 * STAGE_B)      // 131072

// ============ split-bf16 HMMA GEMM, 512 thr / 16 warps, block 128x128 ============
// MODE 0: generic via args. MODE 1: fused embeds, z=0..5 (3 singles + 3 retrieved).
template <int EPI, int OUT, int MODE>
__global__ void __launch_bounds__(512, 1)
hgemm(const __nv_bfloat16* __restrict__ Ap, size_t aLo,
      const __nv_bfloat16* __restrict__ Wp, size_t wLo,
      const float* __restrict__ bias,
      void* __restrict__ Cp, size_t cLo, int ldC,
      int M, int N, int Kp) {
    const __nv_bfloat16 *Ab, *Wb;
    const float* bb;
    void* Cb;
    size_t aLoOff, wLoOff;
    if (MODE == 1) {
        const int z = blockIdx.z;
        const bool single = z < 3;
        M = single ? BSZ : NRET;
        if (blockIdx.y * 128 >= M) return;
        Ab = single ? g_aS + (size_t)z * (2ull * BSZ * FDIM)
                    : g_aR + (size_t)(z - 3) * (2ull * NRET * FDIM);
        aLoOff = single ? (size_t)BSZ * FDIM : (size_t)NRET * FDIM;
        Wb = g_wE + (size_t)z * (2ull * 512 * FDIM);
        wLoOff = (size_t)512 * FDIM;
        bb = g_bias + z * 512;
        Cb = single ? (void*)(g_E + (size_t)z * BSZ * PDIM)
                    : (void*)(g_Rout + (size_t)(z - 3) * NRET * PDIM);
        ldC = PDIM; N = PDIM; Kp = FDIM;
    } else {
        Ab = Ap; aLoOff = aLo; Wb = Wp; wLoOff = wLo; bb = bias; Cb = Cp;
    }

    extern __shared__ char smem[];
    const uint32_t sb = smem_u32(smem);
    const int tid = threadIdx.x, wid = tid >> 5, lane = tid & 31;
    const int bm = blockIdx.y * 128, bn = blockIdx.x * 128;
    const int wm = (wid & 3) * 32, wn = (wid >> 2) * 32;
    const int nch = Kp >> 5;

    float acc[8][4];
#pragma unroll
    for (int i = 0; i < 8; i++)
#pragma unroll
        for (int j = 0; j < 4; j++) acc[i][j] = 0.f;

    const int frow = tid >> 2, fch = tid & 3;
    const uint32_t fso = swz(frow, fch);
    auto fill = [&](int c) {
        if (c >= nch) return;
        const int k0 = (c << 5) + fch * 8;
        const uint32_t st = sb + (uint32_t)(c & 3) * STAGE_B;
        const size_t aoff = (size_t)(bm + frow) * Kp + k0;
        cpa16(st + fso, Ab + aoff);
        cpa16(st + 8192 + fso, Ab + aLoOff + aoff);
        const size_t woff = (size_t)(bn + frow) * Kp + k0;
        cpa16(st + 16384 + fso, Wb + woff);
        cpa16(st + 24576 + fso, Wb + wLoOff + woff);
    };

    fill(0); cpa_commit();
    fill(1); cpa_commit();
    fill(2); cpa_commit();

    for (int c = 0; c < nch; c++) {
        asm volatile("cp.async.wait_group 2;" ::: "memory");
        __syncthreads();
        fill(c + 3);
        cpa_commit();

        const uint32_t st = sb + (uint32_t)(c & 3) * STAGE_B;
        const uint32_t sAh = st, sAl = st + 8192, sWh = st + 16384, sWl = st + 24576;
#pragma unroll
        for (int ks = 0; ks < 2; ks++) {
            uint32_t ah[2][4], al[2][4], wh[2][4], wl[2][4];
#pragma unroll
            for (int mi = 0; mi < 2; mi++) {
                const int r = wm + mi * 16 + (lane & 15);
                const int cc = 2 * ks + (lane >> 4);
                const uint32_t so = swz(r, cc);
                ldsm4(ah[mi], sAh + so);
                ldsm4(al[mi], sAl + so);
            }
#pragma unroll
            for (int ng = 0; ng < 2; ng++) {
                const int r = wn + ng * 16 + ((lane >> 4) << 3) + (lane & 7);
                const int cc = 2 * ks + ((lane >> 3) & 1);
                const uint32_t so = swz(r, cc);
                ldsm4(wh[ng], sWh + so);
                ldsm4(wl[ng], sWl + so);
            }
#pragma unroll
            for (int mi = 0; mi < 2; mi++)
#pragma unroll
                for (int ng = 0; ng < 2; ng++)
#pragma unroll
                    for (int sub = 0; sub < 2; sub++)
                        mma16816(acc[mi * 4 + ng * 2 + sub], ah[mi], wh[ng][2 * sub], wh[ng][2 * sub + 1]);
#pragma unroll
            for (int mi = 0; mi < 2; mi++)
#pragma unroll
                for (int ng = 0; ng < 2; ng++)
#pragma unroll
                    for (int sub = 0; sub < 2; sub++)
                        mma16816(acc[mi * 4 + ng * 2 + sub], al[mi], wh[ng][2 * sub], wh[ng][2 * sub + 1]);
#pragma unroll
            for (int mi = 0; mi < 2; mi++)
#pragma unroll
                for (int ng = 0; ng < 2; ng++)
#pragma unroll
                    for (int sub = 0; sub < 2; sub++)
                        mma16816(acc[mi * 4 + ng * 2 + sub], ah[mi], wl[ng][2 * sub], wl[ng][2 * sub + 1]);
        }
    }

#pragma unroll
    for (int mi = 0; mi < 2; mi++)
#pragma unroll
        for (int nj = 0; nj < 4; nj++) {
            const float* d = acc[mi * 4 + nj];
            const int gm = bm + wm + mi * 16 + (lane >> 2);
            const int gn = bn + wn + nj * 8 + (lane & 3) * 2;
            if (gn >= N) continue;
            const float b0 = bb[gn], b1 = bb[gn + 1];
#pragma unroll
            for (int half = 0; half < 2; half++) {
                const int gr = gm + half * 8;
                if (gr >= M) continue;
                float v0 = d[half * 2 + 0] + b0;
                float v1 = d[half * 2 + 1] + b1;
                if (EPI == 1) { v0 = tanhf(v0); v1 = tanhf(v1); }
                else if (EPI == 2) { v0 = fmaxf(v0, 0.f); v1 = fmaxf(v1, 0.f); }
                if (OUT == 0) {
                    float2 o; o.x = v0; o.y = v1;
                    *reinterpret_cast<float2*>((float*)Cb + (size_t)gr * ldC + gn) = o;
                } else {
                    __nv_bfloat16* Ch = (__nv_bfloat16*)Cb;
                    const size_t base = (size_t)gr * ldC + gn;
                    const __nv_bfloat16 h0 = __float2bfloat16(v0), h1 = __float2bfloat16(v1);
                    __nv_bfloat162 hp; hp.x = h0; hp.y = h1;
                    __nv_bfloat162 lp;
                    lp.x = __float2bfloat16(v0 - __bfloat162float(h0));
                    lp.y = __float2bfloat16(v1 - __bfloat162float(h1));
                    *reinterpret_cast<__nv_bfloat162*>(Ch + base) = hp;
                    *reinterpret_cast<__nv_bfloat162*>(Ch + cLo + base) = lp;
                }
            }
        }
}

// ---------------- table-driven batched preconvert ----------------
struct ConvJob { const float* src; __nv_bfloat16* dst; int rows, cols, rp, cp; };
struct ConvTable { ConvJob j[12]; long long nG[12]; int n; };

__global__ void conv_batch(ConvTable T, long long total) {
    long long g = (long long)blockIdx.x * blockDim.x + threadIdx.x;
    if (g >= total) return;
    int ji = 0;
    while (g >= T.nG[ji]) { g -= T.nG[ji]; ji++; }
    const ConvJob& J = T.j[ji];
    const int gpr = J.cp >> 3;
    const int row = (int)(g / gpr), c8 = (int)(g % gpr) * 8;
    float v[8];
    if (row < J.rows && c8 + 8 <= J.cols) {
        const float4 a = *reinterpret_cast<const float4*>(J.src + (size_t)row * J.cols + c8);
        const float4 b = *reinterpret_cast<const float4*>(J.src + (size_t)row * J.cols + c8 + 4);
        v[0] = a.x; v[1] = a.y; v[2] = a.z; v[3] = a.w;
        v[4] = b.x; v[5] = b.y; v[6] = b.z; v[7] = b.w;
    } else {
#pragma unroll
        for (int q = 0; q < 8; q++)
            v[q] = (row < J.rows && c8 + q < J.cols) ? J.src[(size_t)row * J.cols + c8 + q] : 0.f;
    }
    uint4 hi, lo;
    __nv_bfloat16* ph = reinterpret_cast<__nv_bfloat16*>(&hi);
    __nv_bfloat16* pl = reinterpret_cast<__nv_bfloat16*>(&lo);
#pragma unroll
    for (int q = 0; q < 8; q++) {
        const __nv_bfloat16 h = __float2bfloat16(v[q]);
        ph[q] = h;
        pl[q] = __float2bfloat16(v[q] - __bfloat162float(h));
    }
    const size_t o = (size_t)row * J.cp + c8;
    *reinterpret_cast<uint4*>(J.dst + o) = hi;
    *reinterpret_cast<uint4*>(J.dst + (size_t)J.rp * J.cp + o) = lo;
}

__global__ void bias_pack(const float* b0, const float* b1, const float* b2,
                          const float* b3, const float* b4, const float* b5,
                          const float* bhg, const float* bp1, const float* bp2) {
    const int t = threadIdx.x;  // 1024
    if (t < 512) {
        g_bias[0 * 512 + t] = (t < PDIM) ? b0[t] : 0.f;
        g_bias[1 * 512 + t] = (t < PDIM) ? b1[t] : 0.f;
        g_bias[2 * 512 + t] = (t < PDIM) ? b2[t] : 0.f;
        g_bias[3 * 512 + t] = (t < PDIM) ? b3[t] : 0.f;
        g_bias[4 * 512 + t] = (t < PDIM) ? b4[t] : 0.f;
        g_bias[5 * 512 + t] = (t < PDIM) ? b5[t] : 0.f;
        g_bias[3072 + t] = (t < ZDIM) ? bhg[t] : 0.f;
    }
    g_bias[3584 + t] = (t < H1D) ? bp1[t] : 0.f;
    if (t < 256) g_bias[4608 + t] = (t < H2D) ? bp2[t] : 0.f;
}

// ---------------- fused retrieved-sum + edge-mean + pair-mean -> g_aM plane ----------------
__global__ void build_means_fused() {
    const int idx = blockIdx.x * blockDim.x + threadIdx.x;
    if (idx >= BSZ * (PDIM / 4)) return;
    const int b = idx / (PDIM / 4), p4 = (idx % (PDIM / 4)) * 4;
    const size_t loOff = (size_t)MROWS_P * KP_HG;

    if (idx < RNUM * (PDIM / 4)) {
        const int i = idx / (PDIM / 4);
        const int q4 = (idx % (PDIM / 4)) * 4;
        float v[4];
#pragma unroll
        for (int j = 0; j < 4; j++) {
            const float a = g_Rout[(size_t)0 * NRET * PDIM + (size_t)i * PDIM + q4 + j];
            const float c = g_Rout[(size_t)1 * NRET * PDIM + (size_t)i * PDIM + q4 + j];
            v[j] = 0.5f * (a + c);
        }
        uint2 hi, lo;
        pack4(v, hi, lo);
        const size_t base = (size_t)(EDGE_ROWS + i) * KP_HG + q4;
        *reinterpret_cast<uint2*>(g_aM + base) = hi;
        *reinterpret_cast<uint2*>(g_aM + loOff + base) = lo;
    }

    const float4 et = *reinterpret_cast<const float4*>(g_E + ((size_t)0 * BSZ + b) * PDIM + p4);
    const float4 ev = *reinterpret_cast<const float4*>(g_E + ((size_t)1 * BSZ + b) * PDIM + p4);
    const float4 eu = *reinterpret_cast<const float4*>(g_E + ((size_t)2 * BSZ + b) * PDIM + p4);

    float4 S[3];
#pragma unroll
    for (int s = 0; s < 3; s++) {
        const float* base = g_Rout + (size_t)s * NRET * PDIM + (size_t)b * RNUM * PDIM + p4;
        float4 a = make_float4(0.f, 0.f, 0.f, 0.f);
#pragma unroll
        for (int i = 0; i < RNUM; i++) {
            const float4 v = *reinterpret_cast<const float4*>(base + (size_t)i * PDIM);
            a.x += v.x; a.y += v.y; a.z += v.z; a.w += v.w;
        }
        S[s] = a;
    }
    const float i3 = 1.f / 3.f, i11 = 1.f / 11.f;
    float o[4][4];
    o[0][0] = (et.x + ev.x + eu.x) * i3; o[0][1] = (et.y + ev.y + eu.y) * i3;
    o[0][2] = (et.z + ev.z + eu.z) * i3; o[0][3] = (et.w + ev.w + eu.w) * i3;
    o[1][0] = (S[0].x + et.x) * i11; o[1][1] = (S[0].y + et.y) * i11;
    o[1][2] = (S[0].z + et.z) * i11; o[1][3] = (S[0].w + et.w) * i11;
    o[2][0] = (S[1].x + ev.x) * i11; o[2][1] = (S[1].y + ev.y) * i11;
    o[2][2] = (S[1].z + ev.z) * i11; o[2][3] = (S[1].w + ev.w) * i11;
    o[3][0] = (S[2].x + eu.x) * i11; o[3][1] = (S[2].y + eu.y) * i11;
    o[3][2] = (S[2].z + eu.z) * i11; o[3][3] = (S[2].w + eu.w) * i11;
#pragma unroll
    for (int e = 0; e < 4; e++) {
        uint2 hi, lo;
        pack4(o[e], hi, lo);
        const size_t base = (size_t)(b * 4 + e) * KP_HG + p4;
        *reinterpret_cast<uint2*>(g_aM + base) = hi;
        *reinterpret_cast<uint2*>(g_aM + loOff + base) = lo;
    }
}

// ---------------- feature assembly -> g_aF plane ----------------
__global__ void build_feat(const float* __restrict__ similarity,
                           const float* __restrict__ rlabel,
                           const float* __restrict__ lbl_w,
                           const float* __restrict__ lbl_b) {
    const int b = blockIdx.x;
    __shared__ float ssim[RNUM];
    __shared__ float s_lbl;
    if (threadIdx.x == 0) {
        float v[RNUM], mx = -1e30f;
#pragma unroll
        for (int i = 0; i < RNUM; i++) { v[i] = similarity[b * RNUM + i]; mx = fmaxf(mx, v[i]); }
        float sum = 0.f;
#pragma unroll
        for (int i = 0; i < RNUM; i++) { v[i] = expf(v[i] - mx); sum += v[i]; }
        float la = 0.f;
        const float inv = 1.f / sum;
#pragma unroll
        for (int i = 0; i < RNUM; i++) {
            v[i] *= inv; ssim[i] = v[i];
            la += v[i] * rlabel[b * RNUM + i];
        }
        s_lbl = la;
    }
    __syncthreads();
    const float* Yb = g_Y + (size_t)b * 4 * ZDIM;
    const float lagg = s_lbl;
    const size_t rb = (size_t)b * KP_P1;
    const size_t loOff = (size_t)BSZ * KP_P1;
    for (int z = threadIdx.x; z < ZDIM; z += blockDim.x) {
        const float Y0 = Yb[z], Y1 = Yb[ZDIM + z], Y2 = Yb[2 * ZDIM + z], Y3 = Yb[3 * ZDIM + z];
        float f[7];
        f[0] = fmaxf(0.5f * (Y0 + Y1), 0.f);
        f[1] = fmaxf(0.5f * (Y0 + Y2), 0.f);
        f[2] = fmaxf(0.5f * (Y0 + Y3), 0.f);
        float rv, rt;
        if (b != 0) {
            rv = fmaxf(Y2, 0.f);
            rt = fmaxf(Y1, 0.f);
        } else {
            rv = 0.f; rt = 0.f;
#pragma unroll
            for (int i = 0; i < RNUM; i++) {
                const float yp = g_Y[(size_t)(EDGE_ROWS + i) * ZDIM + z];
                rt += ssim[i] * fmaxf(0.5f * (Y1 + yp), 0.f);
                rv += ssim[i] * fmaxf(0.5f * (Y2 + yp), 0.f);
            }
        }
        f[3] = rv;
        f[4] = rt;
        f[5] = fmaxf(Y3, 0.f);
        f[6] = fmaxf(lagg * lbl_w[z] + lbl_b[z], 0.f);
#pragma unroll
        for (int s = 0; s < 7; s++) {
            const size_t o = rb + s * ZDIM + z;
            store_hl(g_aF + o, g_aF + loOff + o, f[s]);
        }
    }
}

__global__ void final_out(const float* __restrict__ p3_w, const float* __restrict__ p3_b,
                          float* __restrict__ out) {
    const int warp = (blockIdx.x * blockDim.x + threadIdx.x) >> 5;
    const int lane = threadIdx.x & 31;
    if (warp >= BSZ) return;
    const float* h = g_h2 + (size_t)warp * H2D;
    float s = 0.f;
    for (int j = lane; j < H2D; j += 32) s += h[j] * p3_w[j];
#pragma unroll
    for (int off = 16; off; off >>= 1) s += __shfl_xor_sync(0xffffffffu, s, off);
    if (lane == 0) out[warp] = 1.f / (1.f + expf(-(s + p3_b[0])));
}

// ---------------- host launcher ----------------
extern "C" void kernel_launch(void* const* d_in, const int* in_sizes, int n_in,
                              void* d_out, int out_size) {
    const float* vis   = (const float*)d_in[0];
    const float* txt   = (const float*)d_in[1];
    const float* sim   = (const float*)d_in[2];
    const float* rvis  = (const float*)d_in[3];
    const float* rtxt  = (const float*)d_in[4];
    const float* rlbl  = (const float*)d_in[5];
    const float* usr   = (const float*)d_in[6];
    const float* rusr  = (const float*)d_in[7];
    const float* vis_w = (const float*)d_in[9],  *vis_b = (const float*)d_in[10];
    const float* txt_w = (const float*)d_in[11], *txt_b = (const float*)d_in[12];
    const float* usr_w = (const float*)d_in[13], *usr_b = (const float*)d_in[14];
    const float* rvis_w = (const float*)d_in[15], *rvis_b = (const float*)d_in[16];
    const float* rtxt_w = (const float*)d_in[17], *rtxt_b = (const float*)d_in[18];
    const float* rusr_w = (const float*)d_in[19], *rusr_b = (const float*)d_in[20];
    const float* hg_w  = (const float*)d_in[21], *hg_b = (const float*)d_in[22];
    const float* lbl_w = (const float*)d_in[23], *lbl_b = (const float*)d_in[24];
    const float* p1_w  = (const float*)d_in[25], *p1_b = (const float*)d_in[26];
    const float* p2_w  = (const float*)d_in[27], *p2_b = (const float*)d_in[28];
    const float* p3_w  = (const float*)d_in[29], *p3_b = (const float*)d_in[30];

    float *Y, *h2, *biasD;
    __nv_bfloat16 *aS, *aR, *wE, *aM, *wHg, *aF, *wP1, *aH1, *wP2;
    cudaGetSymbolAddress((void**)&Y, g_Y);
    cudaGetSymbolAddress((void**)&h2, g_h2);
    cudaGetSymbolAddress((void**)&biasD, g_bias);
    cudaGetSymbolAddress((void**)&aS, g_aS);
    cudaGetSymbolAddress((void**)&aR, g_aR);
    cudaGetSymbolAddress((void**)&wE, g_wE);
    cudaGetSymbolAddress((void**)&aM, g_aM);
    cudaGetSymbolAddress((void**)&wHg, g_wHg);
    cudaGetSymbolAddress((void**)&aF, g_aF);
    cudaGetSymbolAddress((void**)&wP1, g_wP1);
    cudaGetSymbolAddress((void**)&aH1, g_aH1);
    cudaGetSymbolAddress((void**)&wP2, g_wP2);

    cudaFuncSetAttribute(hgemm<1,0,1>, cudaFuncAttributeMaxDynamicSharedMemorySize, SMEM_BYTES);
    cudaFuncSetAttribute(hgemm<0,0,0>, cudaFuncAttributeMaxDynamicSharedMemorySize, SMEM_BYTES);
    cudaFuncSetAttribute(hgemm<2,1,0>, cudaFuncAttributeMaxDynamicSharedMemorySize, SMEM_BYTES);
    cudaFuncSetAttribute(hgemm<2,0,0>, cudaFuncAttributeMaxDynamicSharedMemorySize, SMEM_BYTES);

    const size_t aSz = 2ull * BSZ * FDIM, aRz = 2ull * NRET * FDIM, wEz = 2ull * 512 * FDIM;

    auto run_group = [&](ConvTable& T) {
        long long total = 0;
        for (int i = 0; i < T.n; i++) {
            T.nG[i] = (long long)T.j[i].rp * (T.j[i].cp >> 3);
            total += T.nG[i];
        }
        for (int i = T.n; i < 12; i++) T.nG[i] = 0x7fffffffffffLL;
        conv_batch<<<(unsigned)((total + 255) / 256), 256>>>(T, total);
    };
    {   // group 1: all weights + 3 single A  (launch #1)
        ConvTable T; T.n = 12;
        T.j[0] = {txt_w,  wE + 0 * wEz, PDIM, FDIM, 512, FDIM};
        T.j[1] = {vis_w,  wE + 1 * wEz, PDIM, FDIM, 512, FDIM};
        T.j[2] = {usr_w,  wE + 2 * wEz, PDIM, FDIM, 512, FDIM};
        T.j[3] = {rtxt_w, wE + 3 * wEz, PDIM, FDIM, 512, FDIM};
        T.j[4] = {rvis_w, wE + 4 * wEz, PDIM, FDIM, 512, FDIM};
        T.j[5] = {rusr_w, wE + 5 * wEz, PDIM, FDIM, 512, FDIM};
        T.j[6] = {hg_w, wHg, ZDIM, PDIM, 512, KP_HG};
        T.j[7] = {p1_w, wP1, H1D, FEATD, 1024, KP_P1};
        T.j[8] = {p2_w, wP2, H2D, H1D, 256, KP_P2};
        T.j[9]  = {txt, aS + 0 * aSz, BSZ, FDIM, BSZ, FDIM};
        T.j[10] = {vis, aS + 1 * aSz, BSZ, FDIM, BSZ, FDIM};
        T.j[11] = {usr, aS + 2 * aSz, BSZ, FDIM, BSZ, FDIM};
        run_group(T);
    }
    {   ConvTable T; T.n = 1; T.j[0] = {rtxt, aR + 0 * aRz, NRET, FDIM, NRET, FDIM}; run_group(T); }  // #2
    {   ConvTable T; T.n = 1; T.j[0] = {rvis, aR + 1 * aRz, NRET, FDIM, NRET, FDIM}; run_group(T); }  // #3
    {   ConvTable T; T.n = 1; T.j[0] = {rusr, aR + 2 * aRz, NRET, FDIM, NRET, FDIM}; run_group(T); }  // #4

    bias_pack<<<1, 1024>>>(txt_b, vis_b, usr_b, rtxt_b, rvis_b, rusr_b, hg_b, p1_b, p2_b);  // #5

    // ---- 1) all 6 embeddings, ONE launch (#6 — ncu -s 5 captures this) ----
    hgemm<1,0,1><<<dim3(4, 320, 6), 512, SMEM_BYTES>>>(
        nullptr, 0, nullptr, 0, nullptr, nullptr, 0, 0, 0, 0, 0);

    // ---- 2) means (+pair means) -> g_aM plane ----
    build_means_fused<<<(BSZ * (PDIM / 4) + 255) / 256, 256>>>();

    // ---- 3) hg projection -> g_Y fp32 ----
    hgemm<0,0,0><<<dim3(3, 129, 1), 512, SMEM_BYTES>>>(
        aM, (size_t)MROWS_P * KP_HG, wHg, (size_t)512 * KP_HG,
        biasD + 3072, Y, 0, ZDIM, M_ROWS, ZDIM, KP_HG);

    // ---- 4) feature assembly -> g_aF plane ----
    build_feat<<<BSZ, 256>>>(sim, rlbl, lbl_w, lbl_b);

    // ---- 5) MLP head ----
    hgemm<2,1,0><<<dim3(7, 32, 1), 512, SMEM_BYTES>>>(
        aF, (size_t)BSZ * KP_P1, wP1, (size_t)1024 * KP_P1,
        biasD + 3584, aH1, (size_t)BSZ * KP_P2, KP_P2, BSZ, H1D, KP_P1);
    hgemm<2,0,0><<<dim3(2, 32, 1), 512, SMEM_BYTES>>>(
        aH1, (size_t)BSZ * KP_P2, wP2, (size_t)256 * KP_P2,
        biasD + 4608, h2, 0, H2D, BSZ, H2D, KP_P2);

    final_out<<<(BSZ * 32 + 255) / 256, 256>>>(p3_w, p3_b, (float*)d_out);
}

// round 13
// speedup vs baseline: 1.4187x; 1.4187x over previous
#include <cuda_runtime.h>
#include <cuda_bf16.h>
#include <cstdint>
#include <math.h>

#define BSZ 4096
#define FDIM 768
#define PDIM 500
#define ZDIM 300
#define RNUM 10
#define NRET (BSZ * RNUM)          // 40960
#define EDGE_ROWS (BSZ * 4)        // 16384
#define M_ROWS (EDGE_ROWS + RNUM)  // 16394
#define FEATD 2100
#define H1D 800
#define H2D 200

#define MROWS_P 16512              // 129*128
#define KP_HG 512
#define KP_P1 2112
#define KP_P2 800

// ---------------- fp32 scratch ----------------
__device__ float g_Rout[3ull * NRET * PDIM];
__device__ float g_E[3ull * BSZ * PDIM];
__device__ float g_Y[(size_t)M_ROWS * ZDIM];
__device__ float g_h2[(size_t)BSZ * H2D];
__device__ float g_bias[8192];
// [0..3072) 6x512 embed biases, [3072..3584) hg, [3584..4608) p1, [4608..4864) p2

// ---------------- bf16 hi/lo planes ----------------
__device__ __align__(16) __nv_bfloat16 g_aS[3ull * 2 * BSZ * FDIM];
__device__ __align__(16) __nv_bfloat16 g_aR[3ull * 2 * NRET * FDIM];
__device__ __align__(16) __nv_bfloat16 g_wE[6ull * 2 * 512 * FDIM];
__device__ __align__(16) __nv_bfloat16 g_aM[2ull * MROWS_P * KP_HG];
__device__ __align__(16) __nv_bfloat16 g_wHg[2ull * 512 * KP_HG];
__device__ __align__(16) __nv_bfloat16 g_aF[2ull * BSZ * KP_P1];
__device__ __align__(16) __nv_bfloat16 g_wP1[2ull * 1024 * KP_P1];
__device__ __align__(16) __nv_bfloat16 g_aH1[2ull * BSZ * KP_P2];
__device__ __align__(16) __nv_bfloat16 g_wP2[2ull * 256 * KP_P2];

// ---------------- helpers ----------------
__device__ __forceinline__ uint32_t smem_u32(const void* p) {
    uint32_t a;
    asm("{ .reg .u64 t; cvta.to.shared.u64 t, %1; cvt.u32.u64 %0, t; }" : "=r"(a) : "l"(p));
    return a;
}
__device__ __forceinline__ void ldsm4(uint32_t* r, uint32_t addr) {
    asm volatile("ldmatrix.sync.aligned.m8n8.x4.shared.b16 {%0,%1,%2,%3}, [%4];"
                 : "=r"(r[0]), "=r"(r[1]), "=r"(r[2]), "=r"(r[3]) : "r"(addr));
}
__device__ __forceinline__ void mma16816(float* d, const uint32_t* a, uint32_t b0, uint32_t b1) {
    asm volatile(
        "mma.sync.aligned.m16n8k16.row.col.f32.bf16.bf16.f32 "
        "{%0,%1,%2,%3}, {%4,%5,%6,%7}, {%8,%9}, {%0,%1,%2,%3};"
        : "+f"(d[0]), "+f"(d[1]), "+f"(d[2]), "+f"(d[3])
        : "r"(a[0]), "r"(a[1]), "r"(a[2]), "r"(a[3]), "r"(b0), "r"(b1));
}
__device__ __forceinline__ uint32_t swz(int row, int chunk) {
    return (uint32_t)(row * 64 + ((chunk ^ ((row >> 1) & 3)) << 4));
}
__device__ __forceinline__ void cpa16(uint32_t dst, const void* src) {
    asm volatile("cp.async.cg.shared.global [%0], [%1], 16;" :: "r"(dst), "l"(src));
}
__device__ __forceinline__ void cpa_commit() {
    asm volatile("cp.async.commit_group;" ::: "memory");
}
__device__ __forceinline__ void store_hl(__nv_bfloat16* hi, __nv_bfloat16* lo, float v) {
    const __nv_bfloat16 h = __float2bfloat16(v);
    *hi = h;
    *lo = __float2bfloat16(v - __bfloat162float(h));
}
__device__ __forceinline__ void pack4(const float* v, uint2& hi, uint2& lo) {
    __nv_bfloat16 h[4], l[4];
#pragma unroll
    for (int j = 0; j < 4; j++) {
        h[j] = __float2bfloat16(v[j]);
        l[j] = __float2bfloat16(v[j] - __bfloat162float(h[j]));
    }
    hi.x = ((uint32_t)*(uint16_t*)&h[1] << 16) | *(uint16_t*)&h[0];
    hi.y = ((uint32_t)*(uint16_t*)&h[3] << 16) | *(uint16_t*)&h[2];
    lo.x = ((uint32_t)*(uint16_t*)&l[1] << 16) | *(uint16_t*)&l[0];
    lo.y = ((uint32_t)*(uint16_t*)&l[3] << 16) | *(uint16_t*)&l[2];
}

#define STAGE_B 49152                 // Ahi 8K | Alo 8K | Whi 16K | Wlo 16K
#define SMEM_BYTES (4 * STAGE_B)      // 196608

// ============ split-bf16 HMMA GEMM on preconverted planes (R9 — proven) ============
// block 128x256, 8 warps (warp 64x64), 4-stage cp.async, 3-pass split.
template <int EPI, int OUT>  // EPI: 0 none,1 tanh,2 relu ; OUT: 0 fp32, 1 hi/lo plane
__global__ void __launch_bounds__(256, 1)
hgemm(const __nv_bfloat16* __restrict__ Ap, size_t aZ, size_t aLo,
      const __nv_bfloat16* __restrict__ Wp, size_t wZ, size_t wLo,
      const float* __restrict__ bias, int bStride,
      void* __restrict__ Cp, size_t cZ, size_t cLo, int ldC,
      int M, int N, int Kp) {
    extern __shared__ char smem[];
    const uint32_t sb = smem_u32(smem);
    const int tid = threadIdx.x, wid = tid >> 5, lane = tid & 31;
    const int bm = blockIdx.y * 128, bn = blockIdx.x * 256;
    const int z = blockIdx.z;
    const __nv_bfloat16* Ab = Ap + (size_t)z * aZ;
    const __nv_bfloat16* Wb = Wp + (size_t)z * wZ;
    const float* bb = bias + (size_t)z * bStride;
    const int wm = (wid & 1) * 64, wn = (wid >> 1) * 64;
    const int nch = Kp >> 5;

    float acc[32][4];
#pragma unroll
    for (int i = 0; i < 32; i++)
#pragma unroll
        for (int j = 0; j < 4; j++) acc[i][j] = 0.f;

    auto fill = [&](int c) {
        if (c >= nch) return;
        const int k0 = c << 5;
        const uint32_t st = sb + (uint32_t)(c & 3) * STAGE_B;
#pragma unroll
        for (int i = 0; i < 2; i++) {  // A: 512 granules/half
            const int g = tid + (i << 8);
            const int row = g >> 2, ch = g & 3;
            const uint32_t so = swz(row, ch);
            const size_t off = (size_t)(bm + row) * Kp + k0 + ch * 8;
            cpa16(st + so, Ab + off);
            cpa16(st + 8192 + so, Ab + aLo + off);
        }
#pragma unroll
        for (int i = 0; i < 4; i++) {  // W: 1024 granules/half
            const int g = tid + (i << 8);
            const int row = g >> 2, ch = g & 3;
            const uint32_t so = swz(row, ch);
            const size_t off = (size_t)(bn + row) * Kp + k0 + ch * 8;
            cpa16(st + 16384 + so, Wb + off);
            cpa16(st + 32768 + so, Wb + wLo + off);
        }
    };

    fill(0); cpa_commit();
    fill(1); cpa_commit();
    fill(2); cpa_commit();

    for (int c = 0; c < nch; c++) {
        asm volatile("cp.async.wait_group 2;" ::: "memory");
        __syncthreads();
        fill(c + 3);
        cpa_commit();

        const uint32_t st = sb + (uint32_t)(c & 3) * STAGE_B;
        const uint32_t sAh = st, sAl = st + 8192, sWh = st + 16384, sWl = st + 32768;
#pragma unroll
        for (int ks = 0; ks < 2; ks++) {
            uint32_t ah[4][4], al[4][4];
#pragma unroll
            for (int mi = 0; mi < 4; mi++) {
                const int r = wm + mi * 16 + (lane & 15);
                const int cc = 2 * ks + (lane >> 4);
                const uint32_t so = swz(r, cc);
                ldsm4(ah[mi], sAh + so);
                ldsm4(al[mi], sAl + so);
            }
#pragma unroll
            for (int ng = 0; ng < 4; ng++) {
                const int r = wn + ng * 16 + ((lane >> 4) << 3) + (lane & 7);
                const int cc = 2 * ks + ((lane >> 3) & 1);
                const uint32_t so = swz(r, cc);
                uint32_t wh[4], wl[4];
                ldsm4(wh, sWh + so);
                ldsm4(wl, sWl + so);
                // pass 1: Ahi*Whi (8 independent MMAs)
#pragma unroll
                for (int mi = 0; mi < 4; mi++)
#pragma unroll
                    for (int sub = 0; sub < 2; sub++)
                        mma16816(acc[mi * 8 + ng * 2 + sub], ah[mi], wh[2 * sub], wh[2 * sub + 1]);
                // pass 2: Alo*Whi
#pragma unroll
                for (int mi = 0; mi < 4; mi++)
#pragma unroll
                    for (int sub = 0; sub < 2; sub++)
                        mma16816(acc[mi * 8 + ng * 2 + sub], al[mi], wh[2 * sub], wh[2 * sub + 1]);
                // pass 3: Ahi*Wlo
#pragma unroll
                for (int mi = 0; mi < 4; mi++)
#pragma unroll
                    for (int sub = 0; sub < 2; sub++)
                        mma16816(acc[mi * 8 + ng * 2 + sub], ah[mi], wl[2 * sub], wl[2 * sub + 1]);
            }
        }
    }

    // ---- epilogue ----
#pragma unroll
    for (int mi = 0; mi < 4; mi++)
#pragma unroll
        for (int nj = 0; nj < 8; nj++) {
            const float* d = acc[mi * 8 + nj];
            const int gm = bm + wm + mi * 16 + (lane >> 2);
            const int gn = bn + wn + nj * 8 + (lane & 3) * 2;
            if (gn >= N) continue;
            const float b0 = bb[gn], b1 = bb[gn + 1];
#pragma unroll
            for (int half = 0; half < 2; half++) {
                const int gr = gm + half * 8;
                if (gr >= M) continue;
                float v0 = d[half * 2 + 0] + b0;
                float v1 = d[half * 2 + 1] + b1;
                if (EPI == 1) { v0 = tanhf(v0); v1 = tanhf(v1); }
                else if (EPI == 2) { v0 = fmaxf(v0, 0.f); v1 = fmaxf(v1, 0.f); }
                if (OUT == 0) {
                    float2 o; o.x = v0; o.y = v1;
                    *reinterpret_cast<float2*>((float*)Cp + (size_t)z * cZ + (size_t)gr * ldC + gn) = o;
                } else {
                    __nv_bfloat16* Ch = (__nv_bfloat16*)Cp;
                    const size_t base = (size_t)gr * ldC + gn;
                    const __nv_bfloat16 h0 = __float2bfloat16(v0), h1 = __float2bfloat16(v1);
                    __nv_bfloat162 hp; hp.x = h0; hp.y = h1;
                    __nv_bfloat162 lp;
                    lp.x = __float2bfloat16(v0 - __bfloat162float(h0));
                    lp.y = __float2bfloat16(v1 - __bfloat162float(h1));
                    *reinterpret_cast<__nv_bfloat162*>(Ch + base) = hp;
                    *reinterpret_cast<__nv_bfloat162*>(Ch + cLo + base) = lp;
                }
            }
        }
}

// ---------------- table-driven batched preconvert (R11 — measured at roofline) ----------------
struct ConvJob { const float* src; __nv_bfloat16* dst; int rows, cols, rp, cp; };
struct ConvTable { ConvJob j[12]; long long nG[12]; int n; };

__global__ void conv_batch(ConvTable T, long long total) {
    long long g = (long long)blockIdx.x * blockDim.x + threadIdx.x;
    if (g >= total) return;
    int ji = 0;
    while (g >= T.nG[ji]) { g -= T.nG[ji]; ji++; }
    const ConvJob& J = T.j[ji];
    const int gpr = J.cp >> 3;
    const int row = (int)(g / gpr), c8 = (int)(g % gpr) * 8;
    float v[8];
    if (row < J.rows && c8 + 8 <= J.cols) {
        const float4 a = *reinterpret_cast<const float4*>(J.src + (size_t)row * J.cols + c8);
        const float4 b = *reinterpret_cast<const float4*>(J.src + (size_t)row * J.cols + c8 + 4);
        v[0] = a.x; v[1] = a.y; v[2] = a.z; v[3] = a.w;
        v[4] = b.x; v[5] = b.y; v[6] = b.z; v[7] = b.w;
    } else {
#pragma unroll
        for (int q = 0; q < 8; q++)
            v[q] = (row < J.rows && c8 + q < J.cols) ? J.src[(size_t)row * J.cols + c8 + q] : 0.f;
    }
    uint4 hi, lo;
    __nv_bfloat16* ph = reinterpret_cast<__nv_bfloat16*>(&hi);
    __nv_bfloat16* pl = reinterpret_cast<__nv_bfloat16*>(&lo);
#pragma unroll
    for (int q = 0; q < 8; q++) {
        const __nv_bfloat16 h = __float2bfloat16(v[q]);
        ph[q] = h;
        pl[q] = __float2bfloat16(v[q] - __bfloat162float(h));
    }
    const size_t o = (size_t)row * J.cp + c8;
    *reinterpret_cast<uint4*>(J.dst + o) = hi;
    *reinterpret_cast<uint4*>(J.dst + (size_t)J.rp * J.cp + o) = lo;
}

__global__ void bias_pack(const float* b0, const float* b1, const float* b2,
                          const float* b3, const float* b4, const float* b5,
                          const float* bhg, const float* bp1, const float* bp2) {
    const int t = threadIdx.x;  // 1024
    if (t < 512) {
        g_bias[0 * 512 + t] = (t < PDIM) ? b0[t] : 0.f;
        g_bias[1 * 512 + t] = (t < PDIM) ? b1[t] : 0.f;
        g_bias[2 * 512 + t] = (t < PDIM) ? b2[t] : 0.f;
        g_bias[3 * 512 + t] = (t < PDIM) ? b3[t] : 0.f;
        g_bias[4 * 512 + t] = (t < PDIM) ? b4[t] : 0.f;
        g_bias[5 * 512 + t] = (t < PDIM) ? b5[t] : 0.f;
        g_bias[3072 + t] = (t < ZDIM) ? bhg[t] : 0.f;
    }
    g_bias[3584 + t] = (t < H1D) ? bp1[t] : 0.f;
    if (t < 256) g_bias[4608 + t] = (t < H2D) ? bp2[t] : 0.f;
}

// ---------------- fused retrieved-sum + edge-mean + pair-mean -> g_aM plane ----------------
__global__ void build_means_fused() {
    const int idx = blockIdx.x * blockDim.x + threadIdx.x;
    if (idx >= BSZ * (PDIM / 4)) return;
    const int b = idx / (PDIM / 4), p4 = (idx % (PDIM / 4)) * 4;
    const size_t loOff = (size_t)MROWS_P * KP_HG;

    if (idx < RNUM * (PDIM / 4)) {  // pair means (10 rows, sample-0)
        const int i = idx / (PDIM / 4);
        const int q4 = (idx % (PDIM / 4)) * 4;
        float v[4];
#pragma unroll
        for (int j = 0; j < 4; j++) {
            const float a = g_Rout[(size_t)0 * NRET * PDIM + (size_t)i * PDIM + q4 + j];
            const float c = g_Rout[(size_t)1 * NRET * PDIM + (size_t)i * PDIM + q4 + j];
            v[j] = 0.5f * (a + c);
        }
        uint2 hi, lo;
        pack4(v, hi, lo);
        const size_t base = (size_t)(EDGE_ROWS + i) * KP_HG + q4;
        *reinterpret_cast<uint2*>(g_aM + base) = hi;
        *reinterpret_cast<uint2*>(g_aM + loOff + base) = lo;
    }

    const float4 et = *reinterpret_cast<const float4*>(g_E + ((size_t)0 * BSZ + b) * PDIM + p4);
    const float4 ev = *reinterpret_cast<const float4*>(g_E + ((size_t)1 * BSZ + b) * PDIM + p4);
    const float4 eu = *reinterpret_cast<const float4*>(g_E + ((size_t)2 * BSZ + b) * PDIM + p4);

    float4 S[3];
#pragma unroll
    for (int s = 0; s < 3; s++) {
        const float* base = g_Rout + (size_t)s * NRET * PDIM + (size_t)b * RNUM * PDIM + p4;
        float4 a = make_float4(0.f, 0.f, 0.f, 0.f);
#pragma unroll
        for (int i = 0; i < RNUM; i++) {
            const float4 v = *reinterpret_cast<const float4*>(base + (size_t)i * PDIM);
            a.x += v.x; a.y += v.y; a.z += v.z; a.w += v.w;
        }
        S[s] = a;
    }
    const float i3 = 1.f / 3.f, i11 = 1.f / 11.f;
    float o[4][4];
    o[0][0] = (et.x + ev.x + eu.x) * i3; o[0][1] = (et.y + ev.y + eu.y) * i3;
    o[0][2] = (et.z + ev.z + eu.z) * i3; o[0][3] = (et.w + ev.w + eu.w) * i3;
    o[1][0] = (S[0].x + et.x) * i11; o[1][1] = (S[0].y + et.y) * i11;
    o[1][2] = (S[0].z + et.z) * i11; o[1][3] = (S[0].w + et.w) * i11;
    o[2][0] = (S[1].x + ev.x) * i11; o[2][1] = (S[1].y + ev.y) * i11;
    o[2][2] = (S[1].z + ev.z) * i11; o[2][3] = (S[1].w + ev.w) * i11;
    o[3][0] = (S[2].x + eu.x) * i11; o[3][1] = (S[2].y + eu.y) * i11;
    o[3][2] = (S[2].z + eu.z) * i11; o[3][3] = (S[2].w + eu.w) * i11;
#pragma unroll
    for (int e = 0; e < 4; e++) {
        uint2 hi, lo;
        pack4(o[e], hi, lo);
        const size_t base = (size_t)(b * 4 + e) * KP_HG + p4;
        *reinterpret_cast<uint2*>(g_aM + base) = hi;
        *reinterpret_cast<uint2*>(g_aM + loOff + base) = lo;
    }
}

// ---------------- feature assembly -> g_aF plane ----------------
__global__ void build_feat(const float* __restrict__ similarity,
                           const float* __restrict__ rlabel,
                           const float* __restrict__ lbl_w,
                           const float* __restrict__ lbl_b) {
    const int b = blockIdx.x;
    __shared__ float ssim[RNUM];
    __shared__ float s_lbl;
    if (threadIdx.x == 0) {
        float v[RNUM], mx = -1e30f;
#pragma unroll
        for (int i = 0; i < RNUM; i++) { v[i] = similarity[b * RNUM + i]; mx = fmaxf(mx, v[i]); }
        float sum = 0.f;
#pragma unroll
        for (int i = 0; i < RNUM; i++) { v[i] = expf(v[i] - mx); sum += v[i]; }
        float la = 0.f;
        const float inv = 1.f / sum;
#pragma unroll
        for (int i = 0; i < RNUM; i++) {
            v[i] *= inv; ssim[i] = v[i];
            la += v[i] * rlabel[b * RNUM + i];
        }
        s_lbl = la;
    }
    __syncthreads();
    const float* Yb = g_Y + (size_t)b * 4 * ZDIM;
    const float lagg = s_lbl;
    const size_t rb = (size_t)b * KP_P1;
    const size_t loOff = (size_t)BSZ * KP_P1;
    for (int z = threadIdx.x; z < ZDIM; z += blockDim.x) {
        const float Y0 = Yb[z], Y1 = Yb[ZDIM + z], Y2 = Yb[2 * ZDIM + z], Y3 = Yb[3 * ZDIM + z];
        float f[7];
        f[0] = fmaxf(0.5f * (Y0 + Y1), 0.f);
        f[1] = fmaxf(0.5f * (Y0 + Y2), 0.f);
        f[2] = fmaxf(0.5f * (Y0 + Y3), 0.f);
        float rv, rt;
        if (b != 0) {
            rv = fmaxf(Y2, 0.f);
            rt = fmaxf(Y1, 0.f);
        } else {
            rv = 0.f; rt = 0.f;
#pragma unroll
            for (int i = 0; i < RNUM; i++) {
                const float yp = g_Y[(size_t)(EDGE_ROWS + i) * ZDIM + z];
                rt += ssim[i] * fmaxf(0.5f * (Y1 + yp), 0.f);
                rv += ssim[i] * fmaxf(0.5f * (Y2 + yp), 0.f);
            }
        }
        f[3] = rv;
        f[4] = rt;
        f[5] = fmaxf(Y3, 0.f);
        f[6] = fmaxf(lagg * lbl_w[z] + lbl_b[z], 0.f);
#pragma unroll
        for (int s = 0; s < 7; s++) {
            const size_t o = rb + s * ZDIM + z;
            store_hl(g_aF + o, g_aF + loOff + o, f[s]);
        }
    }
}

__global__ void final_out(const float* __restrict__ p3_w, const float* __restrict__ p3_b,
                          float* __restrict__ out) {
    const int warp = (blockIdx.x * blockDim.x + threadIdx.x) >> 5;
    const int lane = threadIdx.x & 31;
    if (warp >= BSZ) return;
    const float* h = g_h2 + (size_t)warp * H2D;
    float s = 0.f;
    for (int j = lane; j < H2D; j += 32) s += h[j] * p3_w[j];
#pragma unroll
    for (int off = 16; off; off >>= 1) s += __shfl_xor_sync(0xffffffffu, s, off);
    if (lane == 0) out[warp] = 1.f / (1.f + expf(-(s + p3_b[0])));
}

// ---------------- host launcher ----------------
extern "C" void kernel_launch(void* const* d_in, const int* in_sizes, int n_in,
                              void* d_out, int out_size) {
    const float* vis   = (const float*)d_in[0];
    const float* txt   = (const float*)d_in[1];
    const float* sim   = (const float*)d_in[2];
    const float* rvis  = (const float*)d_in[3];
    const float* rtxt  = (const float*)d_in[4];
    const float* rlbl  = (const float*)d_in[5];
    const float* usr   = (const float*)d_in[6];
    const float* rusr  = (const float*)d_in[7];
    const float* vis_w = (const float*)d_in[9],  *vis_b = (const float*)d_in[10];
    const float* txt_w = (const float*)d_in[11], *txt_b = (const float*)d_in[12];
    const float* usr_w = (const float*)d_in[13], *usr_b = (const float*)d_in[14];
    const float* rvis_w = (const float*)d_in[15], *rvis_b = (const float*)d_in[16];
    const float* rtxt_w = (const float*)d_in[17], *rtxt_b = (const float*)d_in[18];
    const float* rusr_w = (const float*)d_in[19], *rusr_b = (const float*)d_in[20];
    const float* hg_w  = (const float*)d_in[21], *hg_b = (const float*)d_in[22];
    const float* lbl_w = (const float*)d_in[23], *lbl_b = (const float*)d_in[24];
    const float* p1_w  = (const float*)d_in[25], *p1_b = (const float*)d_in[26];
    const float* p2_w  = (const float*)d_in[27], *p2_b = (const float*)d_in[28];
    const float* p3_w  = (const float*)d_in[29], *p3_b = (const float*)d_in[30];

    float *Y, *h2, *biasD, *Rout, *E;
    __nv_bfloat16 *aS, *aR, *wE, *aM, *wHg, *aF, *wP1, *aH1, *wP2;
    cudaGetSymbolAddress((void**)&Rout, g_Rout);
    cudaGetSymbolAddress((void**)&E, g_E);
    cudaGetSymbolAddress((void**)&Y, g_Y);
    cudaGetSymbolAddress((void**)&h2, g_h2);
    cudaGetSymbolAddress((void**)&biasD, g_bias);
    cudaGetSymbolAddress((void**)&aS, g_aS);
    cudaGetSymbolAddress((void**)&aR, g_aR);
    cudaGetSymbolAddress((void**)&wE, g_wE);
    cudaGetSymbolAddress((void**)&aM, g_aM);
    cudaGetSymbolAddress((void**)&wHg, g_wHg);
    cudaGetSymbolAddress((void**)&aF, g_aF);
    cudaGetSymbolAddress((void**)&wP1, g_wP1);
    cudaGetSymbolAddress((void**)&aH1, g_aH1);
    cudaGetSymbolAddress((void**)&wP2, g_wP2);

    cudaFuncSetAttribute(hgemm<1,0>, cudaFuncAttributeMaxDynamicSharedMemorySize, SMEM_BYTES);
    cudaFuncSetAttribute(hgemm<0,0>, cudaFuncAttributeMaxDynamicSharedMemorySize, SMEM_BYTES);
    cudaFuncSetAttribute(hgemm<2,1>, cudaFuncAttributeMaxDynamicSharedMemorySize, SMEM_BYTES);
    cudaFuncSetAttribute(hgemm<2,0>, cudaFuncAttributeMaxDynamicSharedMemorySize, SMEM_BYTES);

    const size_t aSz = 2ull * BSZ * FDIM, aRz = 2ull * NRET * FDIM, wEz = 2ull * 512 * FDIM;

    auto run_group = [&](ConvTable& T) {
        long long total = 0;
        for (int i = 0; i < T.n; i++) {
            T.nG[i] = (long long)T.j[i].rp * (T.j[i].cp >> 3);
            total += T.nG[i];
        }
        for (int i = T.n; i < 12; i++) T.nG[i] = 0x7fffffffffffLL;
        conv_batch<<<(unsigned)((total + 255) / 256), 256>>>(T, total);
    };
    {   // group 1: all weights + 3 single-sample A tensors
        ConvTable T; T.n = 12;
        T.j[0] = {txt_w,  wE + 0 * wEz, PDIM, FDIM, 512, FDIM};
        T.j[1] = {vis_w,  wE + 1 * wEz, PDIM, FDIM, 512, FDIM};
        T.j[2] = {usr_w,  wE + 2 * wEz, PDIM, FDIM, 512, FDIM};
        T.j[3] = {rtxt_w, wE + 3 * wEz, PDIM, FDIM, 512, FDIM};
        T.j[4] = {rvis_w, wE + 4 * wEz, PDIM, FDIM, 512, FDIM};
        T.j[5] = {rusr_w, wE + 5 * wEz, PDIM, FDIM, 512, FDIM};
        T.j[6] = {hg_w, wHg, ZDIM, PDIM, 512, KP_HG};
        T.j[7] = {p1_w, wP1, H1D, FEATD, 1024, KP_P1};
        T.j[8] = {p2_w, wP2, H2D, H1D, 256, KP_P2};
        T.j[9]  = {txt, aS + 0 * aSz, BSZ, FDIM, BSZ, FDIM};
        T.j[10] = {vis, aS + 1 * aSz, BSZ, FDIM, BSZ, FDIM};
        T.j[11] = {usr, aS + 2 * aSz, BSZ, FDIM, BSZ, FDIM};
        run_group(T);
    }
    {   ConvTable T; T.n = 1; T.j[0] = {rtxt, aR + 0 * aRz, NRET, FDIM, NRET, FDIM}; run_group(T); }
    {   ConvTable T; T.n = 1; T.j[0] = {rvis, aR + 1 * aRz, NRET, FDIM, NRET, FDIM}; run_group(T); }
    {   ConvTable T; T.n = 1; T.j[0] = {rusr, aR + 2 * aRz, NRET, FDIM, NRET, FDIM}; run_group(T); }

    bias_pack<<<1, 1024>>>(txt_b, vis_b, usr_b, rtxt_b, rvis_b, rusr_b, hg_b, p1_b, p2_b);

    // ---- 1) embeddings (R9 config: z=3 batched, block 128x256) ----
    hgemm<1,0><<<dim3(2, 32, 3), 256, SMEM_BYTES>>>(
        aS, aSz, (size_t)BSZ * FDIM, wE, wEz, (size_t)512 * FDIM,
        biasD, 512, E, (size_t)BSZ * PDIM, 0, PDIM, BSZ, PDIM, FDIM);
    hgemm<1,0><<<dim3(2, 320, 3), 256, SMEM_BYTES>>>(
        aR, aRz, (size_t)NRET * FDIM, wE + 3 * wEz, wEz, (size_t)512 * FDIM,
        biasD + 3 * 512, 512, Rout, (size_t)NRET * PDIM, 0, PDIM, NRET, PDIM, FDIM);

    // ---- 2) means (+pair means) -> g_aM plane ----
    build_means_fused<<<(BSZ * (PDIM / 4) + 255) / 256, 256>>>();

    // ---- 3) hg projection -> g_Y fp32 ----
    hgemm<0,0><<<dim3(2, 129, 1), 256, SMEM_BYTES>>>(
        aM, 0, (size_t)MROWS_P * KP_HG, wHg, 0, (size_t)512 * KP_HG,
        biasD + 3072, 0, Y, 0, 0, ZDIM, M_ROWS, ZDIM, KP_HG);

    // ---- 4) feature assembly -> g_aF plane ----
    build_feat<<<BSZ, 256>>>(sim, rlbl, lbl_w, lbl_b);

    // ---- 5) MLP head ----
    hgemm<2,1><<<dim3(4, 32, 1), 256, SMEM_BYTES>>>(
        aF, 0, (size_t)BSZ * KP_P1, wP1, 0, (size_t)1024 * KP_P1,
        biasD + 3584, 0, aH1, 0, (size_t)BSZ * KP_P2, KP_P2, BSZ, H1D, KP_P1);
    hgemm<2,0><<<dim3(1, 32, 1), 256, SMEM_BYTES>>>(
        aH1, 0, (size_t)BSZ * KP_P2, wP2, 0, (size_t)256 * KP_P2,
        biasD + 4608, 0, h2, 0, 0, H2D, BSZ, H2D, KP_P2);

    final_out<<<(BSZ * 32 + 255) / 256, 256>>>(p3_w, p3_b, (float*)d_out);
}

// round 14
// speedup vs baseline: 1.8288x; 1.2891x over previous
#include <cuda_runtime.h>
#include <cuda_fp16.h>
#include <cstdint>
#include <math.h>

#define BSZ 4096
#define FDIM 768
#define PDIM 500
#define ZDIM 300
#define RNUM 10
#define NRET (BSZ * RNUM)          // 40960
#define EDGE_ROWS (BSZ * 4)        // 16384
#define M_ROWS (EDGE_ROWS + RNUM)  // 16394
#define FEATD 2100
#define H1D 800
#define H2D 200

#define MROWS_P 16512              // 129*128
#define KP_HG 512
#define KP_P1 2112
#define KP_P2 800

// ---------------- fp32 scratch ----------------
__device__ float g_Rout[3ull * NRET * PDIM];
__device__ float g_E[3ull * BSZ * PDIM];
__device__ float g_Y[(size_t)M_ROWS * ZDIM];
__device__ float g_h2[(size_t)BSZ * H2D];
__device__ float g_bias[8192];
// [0..3072) 6x512 embed biases, [3072..3584) hg, [3584..4608) p1, [4608..4864) p2

// ---------------- fp16 planes: A matrices hi+lo, W matrices single ----------------
__device__ __align__(16) __half g_aS[3ull * 2 * BSZ * FDIM];
__device__ __align__(16) __half g_aR[3ull * 2 * NRET * FDIM];
__device__ __align__(16) __half g_wE[6ull * 512 * FDIM];
__device__ __align__(16) __half g_aM[2ull * MROWS_P * KP_HG];
__device__ __align__(16) __half g_wHg[(size_t)512 * KP_HG];
__device__ __align__(16) __half g_aF[2ull * BSZ * KP_P1];
__device__ __align__(16) __half g_wP1[(size_t)1024 * KP_P1];
__device__ __align__(16) __half g_aH1[2ull * BSZ * KP_P2];
__device__ __align__(16) __half g_wP2[(size_t)256 * KP_P2];

// ---------------- helpers ----------------
__device__ __forceinline__ uint32_t smem_u32(const void* p) {
    uint32_t a;
    asm("{ .reg .u64 t; cvta.to.shared.u64 t, %1; cvt.u32.u64 %0, t; }" : "=r"(a) : "l"(p));
    return a;
}
__device__ __forceinline__ void ldsm4(uint32_t* r, uint32_t addr) {
    asm volatile("ldmatrix.sync.aligned.m8n8.x4.shared.b16 {%0,%1,%2,%3}, [%4];"
                 : "=r"(r[0]), "=r"(r[1]), "=r"(r[2]), "=r"(r[3]) : "r"(addr));
}
__device__ __forceinline__ void mma16816(float* d, const uint32_t* a, uint32_t b0, uint32_t b1) {
    asm volatile(
        "mma.sync.aligned.m16n8k16.row.col.f32.f16.f16.f32 "
        "{%0,%1,%2,%3}, {%4,%5,%6,%7}, {%8,%9}, {%0,%1,%2,%3};"
        : "+f"(d[0]), "+f"(d[1]), "+f"(d[2]), "+f"(d[3])
        : "r"(a[0]), "r"(a[1]), "r"(a[2]), "r"(a[3]), "r"(b0), "r"(b1));
}
__device__ __forceinline__ uint32_t swz(int row, int chunk) {
    return (uint32_t)(row * 64 + ((chunk ^ ((row >> 1) & 3)) << 4));
}
__device__ __forceinline__ void cpa16(uint32_t dst, const void* src) {
    asm volatile("cp.async.cg.shared.global [%0], [%1], 16;" :: "r"(dst), "l"(src));
}
__device__ __forceinline__ void cpa_commit() {
    asm volatile("cp.async.commit_group;" ::: "memory");
}
__device__ __forceinline__ void store_hlh(__half* hi, __half* lo, float v) {
    const __half h = __float2half_rn(v);
    *hi = h;
    *lo = __float2half_rn(v - __half2float(h));
}
__device__ __forceinline__ uint16_t h2u(__half h) { return *reinterpret_cast<uint16_t*>(&h); }
__device__ __forceinline__ void pack4h(const float* v, uint2& hi, uint2& lo) {
    __half h[4], l[4];
#pragma unroll
    for (int j = 0; j < 4; j++) {
        h[j] = __float2half_rn(v[j]);
        l[j] = __float2half_rn(v[j] - __half2float(h[j]));
    }
    hi.x = ((uint32_t)h2u(h[1]) << 16) | h2u(h[0]);
    hi.y = ((uint32_t)h2u(h[3]) << 16) | h2u(h[2]);
    lo.x = ((uint32_t)h2u(l[1]) << 16) | h2u(l[0]);
    lo.y = ((uint32_t)h2u(l[3]) << 16) | h2u(l[2]);
}

#define STAGE_B 32768                 // Ahi 8K | Alo 8K | W 16K
#define SMEM_BYTES (4 * STAGE_B)      // 131072

// ============ split-fp16 HMMA GEMM: C = epi(A @ W^T + bias), 2-pass ============
// block 128x256, 8 warps (warp 64x64), 4-stage cp.async.
// D = Ahi*Wf + Alo*Wf  (residual error = A*(W - Wf) ~ 1.4e-4 rel)
template <int EPI, int OUT>  // EPI: 0 none,1 tanh,2 relu ; OUT: 0 fp32, 1 fp16 hi/lo plane
__global__ void __launch_bounds__(256, 1)
hgemm(const __half* __restrict__ Ap, size_t aZ, size_t aLo,
      const __half* __restrict__ Wp, size_t wZ,
      const float* __restrict__ bias, int bStride,
      void* __restrict__ Cp, size_t cZ, size_t cLo, int ldC,
      int M, int N, int Kp) {
    extern __shared__ char smem[];
    const uint32_t sb = smem_u32(smem);
    const int tid = threadIdx.x, wid = tid >> 5, lane = tid & 31;
    const int bm = blockIdx.y * 128, bn = blockIdx.x * 256;
    const int z = blockIdx.z;
    const __half* Ab = Ap + (size_t)z * aZ;
    const __half* Wb = Wp + (size_t)z * wZ;
    const float* bb = bias + (size_t)z * bStride;
    const int wm = (wid & 1) * 64, wn = (wid >> 1) * 64;
    const int nch = Kp >> 5;

    float acc[32][4];
#pragma unroll
    for (int i = 0; i < 32; i++)
#pragma unroll
        for (int j = 0; j < 4; j++) acc[i][j] = 0.f;

    auto fill = [&](int c) {
        if (c >= nch) return;
        const int k0 = c << 5;
        const uint32_t st = sb + (uint32_t)(c & 3) * STAGE_B;
#pragma unroll
        for (int i = 0; i < 2; i++) {  // A: 512 granules per plane
            const int g = tid + (i << 8);
            const int row = g >> 2, ch = g & 3;
            const uint32_t so = swz(row, ch);
            const size_t off = (size_t)(bm + row) * Kp + k0 + ch * 8;
            cpa16(st + so, Ab + off);
            cpa16(st + 8192 + so, Ab + aLo + off);
        }
#pragma unroll
        for (int i = 0; i < 4; i++) {  // W single: 1024 granules
            const int g = tid + (i << 8);
            const int row = g >> 2, ch = g & 3;
            const uint32_t so = swz(row, ch);
            const size_t off = (size_t)(bn + row) * Kp + k0 + ch * 8;
            cpa16(st + 16384 + so, Wb + off);
        }
    };

    fill(0); cpa_commit();
    fill(1); cpa_commit();
    fill(2); cpa_commit();

    for (int c = 0; c < nch; c++) {
        asm volatile("cp.async.wait_group 2;" ::: "memory");
        __syncthreads();
        fill(c + 3);
        cpa_commit();

        const uint32_t st = sb + (uint32_t)(c & 3) * STAGE_B;
        const uint32_t sAh = st, sAl = st + 8192, sW = st + 16384;
#pragma unroll
        for (int ks = 0; ks < 2; ks++) {
            uint32_t ah[4][4], al[4][4];
#pragma unroll
            for (int mi = 0; mi < 4; mi++) {
                const int r = wm + mi * 16 + (lane & 15);
                const int cc = 2 * ks + (lane >> 4);
                const uint32_t so = swz(r, cc);
                ldsm4(ah[mi], sAh + so);
                ldsm4(al[mi], sAl + so);
            }
#pragma unroll
            for (int ng = 0; ng < 4; ng++) {
                const int r = wn + ng * 16 + ((lane >> 4) << 3) + (lane & 7);
                const int cc = 2 * ks + ((lane >> 3) & 1);
                const uint32_t so = swz(r, cc);
                uint32_t w[4];
                ldsm4(w, sW + so);
                // pass 1: Ahi*W (8 independent MMAs)
#pragma unroll
                for (int mi = 0; mi < 4; mi++)
#pragma unroll
                    for (int sub = 0; sub < 2; sub++)
                        mma16816(acc[mi * 8 + ng * 2 + sub], ah[mi], w[2 * sub], w[2 * sub + 1]);
                // pass 2: Alo*W
#pragma unroll
                for (int mi = 0; mi < 4; mi++)
#pragma unroll
                    for (int sub = 0; sub < 2; sub++)
                        mma16816(acc[mi * 8 + ng * 2 + sub], al[mi], w[2 * sub], w[2 * sub + 1]);
            }
        }
    }

    // ---- epilogue ----
#pragma unroll
    for (int mi = 0; mi < 4; mi++)
#pragma unroll
        for (int nj = 0; nj < 8; nj++) {
            const float* d = acc[mi * 8 + nj];
            const int gm = bm + wm + mi * 16 + (lane >> 2);
            const int gn = bn + wn + nj * 8 + (lane & 3) * 2;
            if (gn >= N) continue;
            const float b0 = bb[gn], b1 = bb[gn + 1];
#pragma unroll
            for (int half = 0; half < 2; half++) {
                const int gr = gm + half * 8;
                if (gr >= M) continue;
                float v0 = d[half * 2 + 0] + b0;
                float v1 = d[half * 2 + 1] + b1;
                if (EPI == 1) { v0 = tanhf(v0); v1 = tanhf(v1); }
                else if (EPI == 2) { v0 = fmaxf(v0, 0.f); v1 = fmaxf(v1, 0.f); }
                if (OUT == 0) {
                    float2 o; o.x = v0; o.y = v1;
                    *reinterpret_cast<float2*>((float*)Cp + (size_t)z * cZ + (size_t)gr * ldC + gn) = o;
                } else {
                    __half* Ch = (__half*)Cp;
                    const size_t base = (size_t)gr * ldC + gn;
                    const __half h0 = __float2half_rn(v0), h1 = __float2half_rn(v1);
                    const __half l0 = __float2half_rn(v0 - __half2float(h0));
                    const __half l1 = __float2half_rn(v1 - __half2float(h1));
                    uint32_t hp = ((uint32_t)h2u(h1) << 16) | h2u(h0);
                    uint32_t lp = ((uint32_t)h2u(l1) << 16) | h2u(l0);
                    *reinterpret_cast<uint32_t*>(Ch + base) = hp;
                    *reinterpret_cast<uint32_t*>(Ch + cLo + base) = lp;
                }
            }
        }
}

// ---------------- table-driven batched preconvert ----------------
// split=1: write fp16 hi plane + lo plane; split=0: single fp16 plane.
struct ConvJob { const float* src; __half* dst; int rows, cols, rp, cp, split; };
struct ConvTable { ConvJob j[12]; long long nG[12]; int n; };

__global__ void conv_batch(ConvTable T, long long total) {
    long long g = (long long)blockIdx.x * blockDim.x + threadIdx.x;
    if (g >= total) return;
    int ji = 0;
    while (g >= T.nG[ji]) { g -= T.nG[ji]; ji++; }
    const ConvJob& J = T.j[ji];
    const int gpr = J.cp >> 3;
    const int row = (int)(g / gpr), c8 = (int)(g % gpr) * 8;
    float v[8];
    if (row < J.rows && c8 + 8 <= J.cols) {
        const float4 a = *reinterpret_cast<const float4*>(J.src + (size_t)row * J.cols + c8);
        const float4 b = *reinterpret_cast<const float4*>(J.src + (size_t)row * J.cols + c8 + 4);
        v[0] = a.x; v[1] = a.y; v[2] = a.z; v[3] = a.w;
        v[4] = b.x; v[5] = b.y; v[6] = b.z; v[7] = b.w;
    } else {
#pragma unroll
        for (int q = 0; q < 8; q++)
            v[q] = (row < J.rows && c8 + q < J.cols) ? J.src[(size_t)row * J.cols + c8 + q] : 0.f;
    }
    uint4 hi, lo;
    __half* ph = reinterpret_cast<__half*>(&hi);
    __half* pl = reinterpret_cast<__half*>(&lo);
#pragma unroll
    for (int q = 0; q < 8; q++) {
        const __half h = __float2half_rn(v[q]);
        ph[q] = h;
        pl[q] = __float2half_rn(v[q] - __half2float(h));
    }
    const size_t o = (size_t)row * J.cp + c8;
    *reinterpret_cast<uint4*>(J.dst + o) = hi;
    if (J.split)
        *reinterpret_cast<uint4*>(J.dst + (size_t)J.rp * J.cp + o) = lo;
}

__global__ void bias_pack(const float* b0, const float* b1, const float* b2,
                          const float* b3, const float* b4, const float* b5,
                          const float* bhg, const float* bp1, const float* bp2) {
    const int t = threadIdx.x;  // 1024
    if (t < 512) {
        g_bias[0 * 512 + t] = (t < PDIM) ? b0[t] : 0.f;
        g_bias[1 * 512 + t] = (t < PDIM) ? b1[t] : 0.f;
        g_bias[2 * 512 + t] = (t < PDIM) ? b2[t] : 0.f;
        g_bias[3 * 512 + t] = (t < PDIM) ? b3[t] : 0.f;
        g_bias[4 * 512 + t] = (t < PDIM) ? b4[t] : 0.f;
        g_bias[5 * 512 + t] = (t < PDIM) ? b5[t] : 0.f;
        g_bias[3072 + t] = (t < ZDIM) ? bhg[t] : 0.f;
    }
    g_bias[3584 + t] = (t < H1D) ? bp1[t] : 0.f;
    if (t < 256) g_bias[4608 + t] = (t < H2D) ? bp2[t] : 0.f;
}

// ---------------- fused retrieved-sum + edge-mean + pair-mean -> g_aM (fp16 hi/lo) ----------------
__global__ void build_means_fused() {
    const int idx = blockIdx.x * blockDim.x + threadIdx.x;
    if (idx >= BSZ * (PDIM / 4)) return;
    const int b = idx / (PDIM / 4), p4 = (idx % (PDIM / 4)) * 4;
    const size_t loOff = (size_t)MROWS_P * KP_HG;

    if (idx < RNUM * (PDIM / 4)) {  // pair means (10 rows, sample-0)
        const int i = idx / (PDIM / 4);
        const int q4 = (idx % (PDIM / 4)) * 4;
        float v[4];
#pragma unroll
        for (int j = 0; j < 4; j++) {
            const float a = g_Rout[(size_t)0 * NRET * PDIM + (size_t)i * PDIM + q4 + j];
            const float c = g_Rout[(size_t)1 * NRET * PDIM + (size_t)i * PDIM + q4 + j];
            v[j] = 0.5f * (a + c);
        }
        uint2 hi, lo;
        pack4h(v, hi, lo);
        const size_t base = (size_t)(EDGE_ROWS + i) * KP_HG + q4;
        *reinterpret_cast<uint2*>(g_aM + base) = hi;
        *reinterpret_cast<uint2*>(g_aM + loOff + base) = lo;
    }

    const float4 et = *reinterpret_cast<const float4*>(g_E + ((size_t)0 * BSZ + b) * PDIM + p4);
    const float4 ev = *reinterpret_cast<const float4*>(g_E + ((size_t)1 * BSZ + b) * PDIM + p4);
    const float4 eu = *reinterpret_cast<const float4*>(g_E + ((size_t)2 * BSZ + b) * PDIM + p4);

    float4 S[3];
#pragma unroll
    for (int s = 0; s < 3; s++) {
        const float* base = g_Rout + (size_t)s * NRET * PDIM + (size_t)b * RNUM * PDIM + p4;
        float4 a = make_float4(0.f, 0.f, 0.f, 0.f);
#pragma unroll
        for (int i = 0; i < RNUM; i++) {
            const float4 v = *reinterpret_cast<const float4*>(base + (size_t)i * PDIM);
            a.x += v.x; a.y += v.y; a.z += v.z; a.w += v.w;
        }
        S[s] = a;
    }
    const float i3 = 1.f / 3.f, i11 = 1.f / 11.f;
    float o[4][4];
    o[0][0] = (et.x + ev.x + eu.x) * i3; o[0][1] = (et.y + ev.y + eu.y) * i3;
    o[0][2] = (et.z + ev.z + eu.z) * i3; o[0][3] = (et.w + ev.w + eu.w) * i3;
    o[1][0] = (S[0].x + et.x) * i11; o[1][1] = (S[0].y + et.y) * i11;
    o[1][2] = (S[0].z + et.z) * i11; o[1][3] = (S[0].w + et.w) * i11;
    o[2][0] = (S[1].x + ev.x) * i11; o[2][1] = (S[1].y + ev.y) * i11;
    o[2][2] = (S[1].z + ev.z) * i11; o[2][3] = (S[1].w + ev.w) * i11;
    o[3][0] = (S[2].x + eu.x) * i11; o[3][1] = (S[2].y + eu.y) * i11;
    o[3][2] = (S[2].z + eu.z) * i11; o[3][3] = (S[2].w + eu.w) * i11;
#pragma unroll
    for (int e = 0; e < 4; e++) {
        uint2 hi, lo;
        pack4h(o[e], hi, lo);
        const size_t base = (size_t)(b * 4 + e) * KP_HG + p4;
        *reinterpret_cast<uint2*>(g_aM + base) = hi;
        *reinterpret_cast<uint2*>(g_aM + loOff + base) = lo;
    }
}

// ---------------- feature assembly -> g_aF (fp16 hi/lo) ----------------
__global__ void build_feat(const float* __restrict__ similarity,
                           const float* __restrict__ rlabel,
                           const float* __restrict__ lbl_w,
                           const float* __restrict__ lbl_b) {
    const int b = blockIdx.x;
    __shared__ float ssim[RNUM];
    __shared__ float s_lbl;
    if (threadIdx.x == 0) {
        float v[RNUM], mx = -1e30f;
#pragma unroll
        for (int i = 0; i < RNUM; i++) { v[i] = similarity[b * RNUM + i]; mx = fmaxf(mx, v[i]); }
        float sum = 0.f;
#pragma unroll
        for (int i = 0; i < RNUM; i++) { v[i] = expf(v[i] - mx); sum += v[i]; }
        float la = 0.f;
        const float inv = 1.f / sum;
#pragma unroll
        for (int i = 0; i < RNUM; i++) {
            v[i] *= inv; ssim[i] = v[i];
            la += v[i] * rlabel[b * RNUM + i];
        }
        s_lbl = la;
    }
    __syncthreads();
    const float* Yb = g_Y + (size_t)b * 4 * ZDIM;
    const float lagg = s_lbl;
    const size_t rb = (size_t)b * KP_P1;
    const size_t loOff = (size_t)BSZ * KP_P1;
    for (int z = threadIdx.x; z < ZDIM; z += blockDim.x) {
        const float Y0 = Yb[z], Y1 = Yb[ZDIM + z], Y2 = Yb[2 * ZDIM + z], Y3 = Yb[3 * ZDIM + z];
        float f[7];
        f[0] = fmaxf(0.5f * (Y0 + Y1), 0.f);
        f[1] = fmaxf(0.5f * (Y0 + Y2), 0.f);
        f[2] = fmaxf(0.5f * (Y0 + Y3), 0.f);
        float rv, rt;
        if (b != 0) {
            rv = fmaxf(Y2, 0.f);
            rt = fmaxf(Y1, 0.f);
        } else {
            rv = 0.f; rt = 0.f;
#pragma unroll
            for (int i = 0; i < RNUM; i++) {
                const float yp = g_Y[(size_t)(EDGE_ROWS + i) * ZDIM + z];
                rt += ssim[i] * fmaxf(0.5f * (Y1 + yp), 0.f);
                rv += ssim[i] * fmaxf(0.5f * (Y2 + yp), 0.f);
            }
        }
        f[3] = rv;
        f[4] = rt;
        f[5] = fmaxf(Y3, 0.f);
        f[6] = fmaxf(lagg * lbl_w[z] + lbl_b[z], 0.f);
#pragma unroll
        for (int s = 0; s < 7; s++) {
            const size_t o = rb + s * ZDIM + z;
            store_hlh(g_aF + o, g_aF + loOff + o, f[s]);
        }
    }
}

__global__ void final_out(const float* __restrict__ p3_w, const float* __restrict__ p3_b,
                          float* __restrict__ out) {
    const int warp = (blockIdx.x * blockDim.x + threadIdx.x) >> 5;
    const int lane = threadIdx.x & 31;
    if (warp >= BSZ) return;
    const float* h = g_h2 + (size_t)warp * H2D;
    float s = 0.f;
    for (int j = lane; j < H2D; j += 32) s += h[j] * p3_w[j];
#pragma unroll
    for (int off = 16; off; off >>= 1) s += __shfl_xor_sync(0xffffffffu, s, off);
    if (lane == 0) out[warp] = 1.f / (1.f + expf(-(s + p3_b[0])));
}

// ---------------- host launcher ----------------
extern "C" void kernel_launch(void* const* d_in, const int* in_sizes, int n_in,
                              void* d_out, int out_size) {
    const float* vis   = (const float*)d_in[0];
    const float* txt   = (const float*)d_in[1];
    const float* sim   = (const float*)d_in[2];
    const float* rvis  = (const float*)d_in[3];
    const float* rtxt  = (const float*)d_in[4];
    const float* rlbl  = (const float*)d_in[5];
    const float* usr   = (const float*)d_in[6];
    const float* rusr  = (const float*)d_in[7];
    const float* vis_w = (const float*)d_in[9],  *vis_b = (const float*)d_in[10];
    const float* txt_w = (const float*)d_in[11], *txt_b = (const float*)d_in[12];
    const float* usr_w = (const float*)d_in[13], *usr_b = (const float*)d_in[14];
    const float* rvis_w = (const float*)d_in[15], *rvis_b = (const float*)d_in[16];
    const float* rtxt_w = (const float*)d_in[17], *rtxt_b = (const float*)d_in[18];
    const float* rusr_w = (const float*)d_in[19], *rusr_b = (const float*)d_in[20];
    const float* hg_w  = (const float*)d_in[21], *hg_b = (const float*)d_in[22];
    const float* lbl_w = (const float*)d_in[23], *lbl_b = (const float*)d_in[24];
    const float* p1_w  = (const float*)d_in[25], *p1_b = (const float*)d_in[26];
    const float* p2_w  = (const float*)d_in[27], *p2_b = (const float*)d_in[28];
    const float* p3_w  = (const float*)d_in[29], *p3_b = (const float*)d_in[30];

    float *Y, *h2, *biasD, *Rout, *E;
    __half *aS, *aR, *wE, *aM, *wHg, *aF, *wP1, *aH1, *wP2;
    cudaGetSymbolAddress((void**)&Rout, g_Rout);
    cudaGetSymbolAddress((void**)&E, g_E);
    cudaGetSymbolAddress((void**)&Y, g_Y);
    cudaGetSymbolAddress((void**)&h2, g_h2);
    cudaGetSymbolAddress((void**)&biasD, g_bias);
    cudaGetSymbolAddress((void**)&aS, g_aS);
    cudaGetSymbolAddress((void**)&aR, g_aR);
    cudaGetSymbolAddress((void**)&wE, g_wE);
    cudaGetSymbolAddress((void**)&aM, g_aM);
    cudaGetSymbolAddress((void**)&wHg, g_wHg);
    cudaGetSymbolAddress((void**)&aF, g_aF);
    cudaGetSymbolAddress((void**)&wP1, g_wP1);
    cudaGetSymbolAddress((void**)&aH1, g_aH1);
    cudaGetSymbolAddress((void**)&wP2, g_wP2);

    cudaFuncSetAttribute(hgemm<1,0>, cudaFuncAttributeMaxDynamicSharedMemorySize, SMEM_BYTES);
    cudaFuncSetAttribute(hgemm<0,0>, cudaFuncAttributeMaxDynamicSharedMemorySize, SMEM_BYTES);
    cudaFuncSetAttribute(hgemm<2,1>, cudaFuncAttributeMaxDynamicSharedMemorySize, SMEM_BYTES);
    cudaFuncSetAttribute(hgemm<2,0>, cudaFuncAttributeMaxDynamicSharedMemorySize, SMEM_BYTES);

    const size_t aSz = 2ull * BSZ * FDIM, aRz = 2ull * NRET * FDIM;
    const size_t wEz = (size_t)512 * FDIM;  // single plane

    auto run_group = [&](ConvTable& T) {
        long long total = 0;
        for (int i = 0; i < T.n; i++) {
            T.nG[i] = (long long)T.j[i].rp * (T.j[i].cp >> 3);
            total += T.nG[i];
        }
        for (int i = T.n; i < 12; i++) T.nG[i] = 0x7fffffffffffLL;
        conv_batch<<<(unsigned)((total + 255) / 256), 256>>>(T, total);
    };
    {   // group 1: all weights (single-plane) + 3 single-sample A (split)
        ConvTable T; T.n = 12;
        T.j[0] = {txt_w,  wE + 0 * wEz, PDIM, FDIM, 512, FDIM, 0};
        T.j[1] = {vis_w,  wE + 1 * wEz, PDIM, FDIM, 512, FDIM, 0};
        T.j[2] = {usr_w,  wE + 2 * wEz, PDIM, FDIM, 512, FDIM, 0};
        T.j[3] = {rtxt_w, wE + 3 * wEz, PDIM, FDIM, 512, FDIM, 0};
        T.j[4] = {rvis_w, wE + 4 * wEz, PDIM, FDIM, 512, FDIM, 0};
        T.j[5] = {rusr_w, wE + 5 * wEz, PDIM, FDIM, 512, FDIM, 0};
        T.j[6] = {hg_w, wHg, ZDIM, PDIM, 512, KP_HG, 0};
        T.j[7] = {p1_w, wP1, H1D, FEATD, 1024, KP_P1, 0};
        T.j[8] = {p2_w, wP2, H2D, H1D, 256, KP_P2, 0};
        T.j[9]  = {txt, aS + 0 * aSz, BSZ, FDIM, BSZ, FDIM, 1};
        T.j[10] = {vis, aS + 1 * aSz, BSZ, FDIM, BSZ, FDIM, 1};
        T.j[11] = {usr, aS + 2 * aSz, BSZ, FDIM, BSZ, FDIM, 1};
        run_group(T);
    }
    {   ConvTable T; T.n = 1; T.j[0] = {rtxt, aR + 0 * aRz, NRET, FDIM, NRET, FDIM, 1}; run_group(T); }
    {   ConvTable T; T.n = 1; T.j[0] = {rvis, aR + 1 * aRz, NRET, FDIM, NRET, FDIM, 1}; run_group(T); }
    {   ConvTable T; T.n = 1; T.j[0] = {rusr, aR + 2 * aRz, NRET, FDIM, NRET, FDIM, 1}; run_group(T); }

    bias_pack<<<1, 1024>>>(txt_b, vis_b, usr_b, rtxt_b, rvis_b, rusr_b, hg_b, p1_b, p2_b);

    // ---- 1) embeddings (z=3 batched, block 128x256, fp16 2-pass) ----
    hgemm<1,0><<<dim3(2, 32, 3), 256, SMEM_BYTES>>>(
        aS, aSz, (size_t)BSZ * FDIM, wE, wEz,
        biasD, 512, E, (size_t)BSZ * PDIM, 0, PDIM, BSZ, PDIM, FDIM);
    hgemm<1,0><<<dim3(2, 320, 3), 256, SMEM_BYTES>>>(
        aR, aRz, (size_t)NRET * FDIM, wE + 3 * wEz, wEz,
        biasD + 3 * 512, 512, Rout, (size_t)NRET * PDIM, 0, PDIM, NRET, PDIM, FDIM);

    // ---- 2) means (+pair means) -> g_aM plane ----
    build_means_fused<<<(BSZ * (PDIM / 4) + 255) / 256, 256>>>();

    // ---- 3) hg projection -> g_Y fp32 ----
    hgemm<0,0><<<dim3(2, 129, 1), 256, SMEM_BYTES>>>(
        aM, 0, (size_t)MROWS_P * KP_HG, wHg, 0,
        biasD + 3072, 0, Y, 0, 0, ZDIM, M_ROWS, ZDIM, KP_HG);

    // ---- 4) feature assembly -> g_aF plane ----
    build_feat<<<BSZ, 256>>>(sim, rlbl, lbl_w, lbl_b);

    // ---- 5) MLP head ----
    hgemm<2,1><<<dim3(4, 32, 1), 256, SMEM_BYTES>>>(
        aF, 0, (size_t)BSZ * KP_P1, wP1, 0,
        biasD + 3584, 0, aH1, 0, (size_t)BSZ * KP_P2, KP_P2, BSZ, H1D, KP_P1);
    hgemm<2,0><<<dim3(1, 32, 1), 256, SMEM_BYTES>>>(
        aH1, 0, (size_t)BSZ * KP_P2, wP2, 0,
        biasD + 4608, 0, h2, 0, 0, H2D, BSZ, H2D, KP_P2);

    final_out<<<(BSZ * 32 + 255) / 256, 256>>>(p3_w, p3_b, (float*)d_out);
}

// round 15
// speedup vs baseline: 1.8452x; 1.0090x over previous
#include <cuda_runtime.h>
#include <cuda_fp16.h>
#include <cstdint>
#include <math.h>

#define BSZ 4096
#define FDIM 768
#define PDIM 500
#define ZDIM 300
#define RNUM 10
#define NRET (BSZ * RNUM)          // 40960
#define EDGE_ROWS (BSZ * 4)        // 16384
#define M_ROWS (EDGE_ROWS + RNUM)  // 16394
#define FEATD 2100
#define H1D 800
#define H2D 200

#define MROWS_P 16512              // 129*128
#define KP_HG 512
#define KP_P1 2112
#define KP_P2 800

// ---------------- fp32 scratch ----------------
__device__ float g_Rout[3ull * NRET * PDIM];
__device__ float g_E[3ull * BSZ * PDIM];
__device__ float g_Y[(size_t)M_ROWS * ZDIM];
__device__ float g_h2[(size_t)BSZ * H2D];
__device__ float g_bias[8192];
// [0..3072) 6x512 embed biases, [3072..3584) hg, [3584..4608) p1, [4608..4864) p2

// ---------------- fp16 planes (single, no split) ----------------
__device__ __align__(16) __half g_aS[3ull * BSZ * FDIM];
__device__ __align__(16) __half g_aR[3ull * NRET * FDIM];
__device__ __align__(16) __half g_wE[6ull * 512 * FDIM];
__device__ __align__(16) __half g_aM[(size_t)MROWS_P * KP_HG];
__device__ __align__(16) __half g_wHg[(size_t)512 * KP_HG];
__device__ __align__(16) __half g_aF[(size_t)BSZ * KP_P1];
__device__ __align__(16) __half g_wP1[(size_t)1024 * KP_P1];
__device__ __align__(16) __half g_aH1[(size_t)BSZ * KP_P2];
__device__ __align__(16) __half g_wP2[(size_t)256 * KP_P2];

// ---------------- helpers ----------------
__device__ __forceinline__ uint32_t smem_u32(const void* p) {
    uint32_t a;
    asm("{ .reg .u64 t; cvta.to.shared.u64 t, %1; cvt.u32.u64 %0, t; }" : "=r"(a) : "l"(p));
    return a;
}
__device__ __forceinline__ void ldsm4(uint32_t* r, uint32_t addr) {
    asm volatile("ldmatrix.sync.aligned.m8n8.x4.shared.b16 {%0,%1,%2,%3}, [%4];"
                 : "=r"(r[0]), "=r"(r[1]), "=r"(r[2]), "=r"(r[3]) : "r"(addr));
}
__device__ __forceinline__ void mma16816(float* d, const uint32_t* a, uint32_t b0, uint32_t b1) {
    asm volatile(
        "mma.sync.aligned.m16n8k16.row.col.f32.f16.f16.f32 "
        "{%0,%1,%2,%3}, {%4,%5,%6,%7}, {%8,%9}, {%0,%1,%2,%3};"
        : "+f"(d[0]), "+f"(d[1]), "+f"(d[2]), "+f"(d[3])
        : "r"(a[0]), "r"(a[1]), "r"(a[2]), "r"(a[3]), "r"(b0), "r"(b1));
}
__device__ __forceinline__ uint32_t swz(int row, int chunk) {
    return (uint32_t)(row * 64 + ((chunk ^ ((row >> 1) & 3)) << 4));
}
__device__ __forceinline__ void cpa16(uint32_t dst, const void* src) {
    asm volatile("cp.async.cg.shared.global [%0], [%1], 16;" :: "r"(dst), "l"(src));
}
__device__ __forceinline__ void cpa_commit() {
    asm volatile("cp.async.commit_group;" ::: "memory");
}
__device__ __forceinline__ uint16_t h2u(__half h) { return *reinterpret_cast<uint16_t*>(&h); }
__device__ __forceinline__ uint2 pack4h(const float* v) {
    __half h[4];
#pragma unroll
    for (int j = 0; j < 4; j++) h[j] = __float2half_rn(v[j]);
    uint2 o;
    o.x = ((uint32_t)h2u(h[1]) << 16) | h2u(h[0]);
    o.y = ((uint32_t)h2u(h[3]) << 16) | h2u(h[2]);
    return o;
}

#define STAGE_B 24576                 // A 8K | W 16K
#define SMEM_BYTES (4 * STAGE_B)      // 98304

// ============ fp16 HMMA GEMM: C = epi(A @ W^T + bias), single pass ============
// block 128x256, 8 warps (warp 64x64), 4-stage cp.async.
template <int EPI, int OUT>  // EPI: 0 none,1 tanh,2 relu ; OUT: 0 fp32, 1 fp16
__global__ void __launch_bounds__(256, 1)
hgemm(const __half* __restrict__ Ap, size_t aZ,
      const __half* __restrict__ Wp, size_t wZ,
      const float* __restrict__ bias, int bStride,
      void* __restrict__ Cp, size_t cZ, int ldC,
      int M, int N, int Kp) {
    extern __shared__ char smem[];
    const uint32_t sb = smem_u32(smem);
    const int tid = threadIdx.x, wid = tid >> 5, lane = tid & 31;
    const int bm = blockIdx.y * 128, bn = blockIdx.x * 256;
    const int z = blockIdx.z;
    const __half* Ab = Ap + (size_t)z * aZ;
    const __half* Wb = Wp + (size_t)z * wZ;
    const float* bb = bias + (size_t)z * bStride;
    const int wm = (wid & 1) * 64, wn = (wid >> 1) * 64;
    const int nch = Kp >> 5;

    float acc[32][4];
#pragma unroll
    for (int i = 0; i < 32; i++)
#pragma unroll
        for (int j = 0; j < 4; j++) acc[i][j] = 0.f;

    auto fill = [&](int c) {
        if (c >= nch) return;
        const int k0 = c << 5;
        const uint32_t st = sb + (uint32_t)(c & 3) * STAGE_B;
#pragma unroll
        for (int i = 0; i < 2; i++) {  // A: 512 granules
            const int g = tid + (i << 8);
            const int row = g >> 2, ch = g & 3;
            const uint32_t so = swz(row, ch);
            const size_t off = (size_t)(bm + row) * Kp + k0 + ch * 8;
            cpa16(st + so, Ab + off);
        }
#pragma unroll
        for (int i = 0; i < 4; i++) {  // W: 1024 granules
            const int g = tid + (i << 8);
            const int row = g >> 2, ch = g & 3;
            const uint32_t so = swz(row, ch);
            const size_t off = (size_t)(bn + row) * Kp + k0 + ch * 8;
            cpa16(st + 8192 + so, Wb + off);
        }
    };

    fill(0); cpa_commit();
    fill(1); cpa_commit();
    fill(2); cpa_commit();

    for (int c = 0; c < nch; c++) {
        asm volatile("cp.async.wait_group 2;" ::: "memory");
        __syncthreads();
        fill(c + 3);
        cpa_commit();

        const uint32_t st = sb + (uint32_t)(c & 3) * STAGE_B;
        const uint32_t sA = st, sW = st + 8192;
#pragma unroll
        for (int ks = 0; ks < 2; ks++) {
            uint32_t ah[4][4];
#pragma unroll
            for (int mi = 0; mi < 4; mi++) {
                const int r = wm + mi * 16 + (lane & 15);
                const int cc = 2 * ks + (lane >> 4);
                ldsm4(ah[mi], sA + swz(r, cc));
            }
#pragma unroll
            for (int ng = 0; ng < 4; ng++) {
                const int r = wn + ng * 16 + ((lane >> 4) << 3) + (lane & 7);
                const int cc = 2 * ks + ((lane >> 3) & 1);
                uint32_t w[4];
                ldsm4(w, sW + swz(r, cc));
#pragma unroll
                for (int mi = 0; mi < 4; mi++)
#pragma unroll
                    for (int sub = 0; sub < 2; sub++)
                        mma16816(acc[mi * 8 + ng * 2 + sub], ah[mi], w[2 * sub], w[2 * sub + 1]);
            }
        }
    }

    // ---- epilogue ----
#pragma unroll
    for (int mi = 0; mi < 4; mi++)
#pragma unroll
        for (int nj = 0; nj < 8; nj++) {
            const float* d = acc[mi * 8 + nj];
            const int gm = bm + wm + mi * 16 + (lane >> 2);
            const int gn = bn + wn + nj * 8 + (lane & 3) * 2;
            if (gn >= N) continue;
            const float b0 = bb[gn], b1 = bb[gn + 1];
#pragma unroll
            for (int half = 0; half < 2; half++) {
                const int gr = gm + half * 8;
                if (gr >= M) continue;
                float v0 = d[half * 2 + 0] + b0;
                float v1 = d[half * 2 + 1] + b1;
                if (EPI == 1) { v0 = tanhf(v0); v1 = tanhf(v1); }
                else if (EPI == 2) { v0 = fmaxf(v0, 0.f); v1 = fmaxf(v1, 0.f); }
                if (OUT == 0) {
                    float2 o; o.x = v0; o.y = v1;
                    *reinterpret_cast<float2*>((float*)Cp + (size_t)z * cZ + (size_t)gr * ldC + gn) = o;
                } else {
                    __half* Ch = (__half*)Cp;
                    const __half h0 = __float2half_rn(v0), h1 = __float2half_rn(v1);
                    const uint32_t hp = ((uint32_t)h2u(h1) << 16) | h2u(h0);
                    *reinterpret_cast<uint32_t*>(Ch + (size_t)gr * ldC + gn) = hp;
                }
            }
        }
}

// ---------------- table-driven batched preconvert (fp32 -> single fp16 plane) ----------------
struct ConvJob { const float* src; __half* dst; int rows, cols, rp, cp; };
struct ConvTable { ConvJob j[12]; long long nG[12]; int n; };

__global__ void conv_batch(ConvTable T, long long total) {
    long long g = (long long)blockIdx.x * blockDim.x + threadIdx.x;
    if (g >= total) return;
    int ji = 0;
    while (g >= T.nG[ji]) { g -= T.nG[ji]; ji++; }
    const ConvJob& J = T.j[ji];
    const int gpr = J.cp >> 3;
    const int row = (int)(g / gpr), c8 = (int)(g % gpr) * 8;
    float v[8];
    if (row < J.rows && c8 + 8 <= J.cols) {
        const float4 a = *reinterpret_cast<const float4*>(J.src + (size_t)row * J.cols + c8);
        const float4 b = *reinterpret_cast<const float4*>(J.src + (size_t)row * J.cols + c8 + 4);
        v[0] = a.x; v[1] = a.y; v[2] = a.z; v[3] = a.w;
        v[4] = b.x; v[5] = b.y; v[6] = b.z; v[7] = b.w;
    } else {
#pragma unroll
        for (int q = 0; q < 8; q++)
            v[q] = (row < J.rows && c8 + q < J.cols) ? J.src[(size_t)row * J.cols + c8 + q] : 0.f;
    }
    uint4 hi;
    __half* ph = reinterpret_cast<__half*>(&hi);
#pragma unroll
    for (int q = 0; q < 8; q++) ph[q] = __float2half_rn(v[q]);
    *reinterpret_cast<uint4*>(J.dst + (size_t)row * J.cp + c8) = hi;
}

__global__ void bias_pack(const float* b0, const float* b1, const float* b2,
                          const float* b3, const float* b4, const float* b5,
                          const float* bhg, const float* bp1, const float* bp2) {
    const int t = threadIdx.x;  // 1024
    if (t < 512) {
        g_bias[0 * 512 + t] = (t < PDIM) ? b0[t] : 0.f;
        g_bias[1 * 512 + t] = (t < PDIM) ? b1[t] : 0.f;
        g_bias[2 * 512 + t] = (t < PDIM) ? b2[t] : 0.f;
        g_bias[3 * 512 + t] = (t < PDIM) ? b3[t] : 0.f;
        g_bias[4 * 512 + t] = (t < PDIM) ? b4[t] : 0.f;
        g_bias[5 * 512 + t] = (t < PDIM) ? b5[t] : 0.f;
        g_bias[3072 + t] = (t < ZDIM) ? bhg[t] : 0.f;
    }
    g_bias[3584 + t] = (t < H1D) ? bp1[t] : 0.f;
    if (t < 256) g_bias[4608 + t] = (t < H2D) ? bp2[t] : 0.f;
}

// ---------------- fused retrieved-sum + edge-mean + pair-mean -> g_aM (fp16) ----------------
__global__ void build_means_fused() {
    const int idx = blockIdx.x * blockDim.x + threadIdx.x;
    if (idx >= BSZ * (PDIM / 4)) return;
    const int b = idx / (PDIM / 4), p4 = (idx % (PDIM / 4)) * 4;

    if (idx < RNUM * (PDIM / 4)) {  // pair means (10 rows, sample-0)
        const int i = idx / (PDIM / 4);
        const int q4 = (idx % (PDIM / 4)) * 4;
        float v[4];
#pragma unroll
        for (int j = 0; j < 4; j++) {
            const float a = g_Rout[(size_t)0 * NRET * PDIM + (size_t)i * PDIM + q4 + j];
            const float c = g_Rout[(size_t)1 * NRET * PDIM + (size_t)i * PDIM + q4 + j];
            v[j] = 0.5f * (a + c);
        }
        *reinterpret_cast<uint2*>(g_aM + (size_t)(EDGE_ROWS + i) * KP_HG + q4) = pack4h(v);
    }

    const float4 et = *reinterpret_cast<const float4*>(g_E + ((size_t)0 * BSZ + b) * PDIM + p4);
    const float4 ev = *reinterpret_cast<const float4*>(g_E + ((size_t)1 * BSZ + b) * PDIM + p4);
    const float4 eu = *reinterpret_cast<const float4*>(g_E + ((size_t)2 * BSZ + b) * PDIM + p4);

    float4 S[3];
#pragma unroll
    for (int s = 0; s < 3; s++) {
        const float* base = g_Rout + (size_t)s * NRET * PDIM + (size_t)b * RNUM * PDIM + p4;
        float4 a = make_float4(0.f, 0.f, 0.f, 0.f);
#pragma unroll
        for (int i = 0; i < RNUM; i++) {
            const float4 v = *reinterpret_cast<const float4*>(base + (size_t)i * PDIM);
            a.x += v.x; a.y += v.y; a.z += v.z; a.w += v.w;
        }
        S[s] = a;
    }
    const float i3 = 1.f / 3.f, i11 = 1.f / 11.f;
    float o[4][4];
    o[0][0] = (et.x + ev.x + eu.x) * i3; o[0][1] = (et.y + ev.y + eu.y) * i3;
    o[0][2] = (et.z + ev.z + eu.z) * i3; o[0][3] = (et.w + ev.w + eu.w) * i3;
    o[1][0] = (S[0].x + et.x) * i11; o[1][1] = (S[0].y + et.y) * i11;
    o[1][2] = (S[0].z + et.z) * i11; o[1][3] = (S[0].w + et.w) * i11;
    o[2][0] = (S[1].x + ev.x) * i11; o[2][1] = (S[1].y + ev.y) * i11;
    o[2][2] = (S[1].z + ev.z) * i11; o[2][3] = (S[1].w + ev.w) * i11;
    o[3][0] = (S[2].x + eu.x) * i11; o[3][1] = (S[2].y + eu.y) * i11;
    o[3][2] = (S[2].z + eu.z) * i11; o[3][3] = (S[2].w + eu.w) * i11;
#pragma unroll
    for (int e = 0; e < 4; e++)
        *reinterpret_cast<uint2*>(g_aM + (size_t)(b * 4 + e) * KP_HG + p4) = pack4h(o[e]);
}

// ---------------- feature assembly -> g_aF (fp16) ----------------
__global__ void build_feat(const float* __restrict__ similarity,
                           const float* __restrict__ rlabel,
                           const float* __restrict__ lbl_w,
                           const float* __restrict__ lbl_b) {
    const int b = blockIdx.x;
    __shared__ float ssim[RNUM];
    __shared__ float s_lbl;
    if (threadIdx.x == 0) {
        float v[RNUM], mx = -1e30f;
#pragma unroll
        for (int i = 0; i < RNUM; i++) { v[i] = similarity[b * RNUM + i]; mx = fmaxf(mx, v[i]); }
        float sum = 0.f;
#pragma unroll
        for (int i = 0; i < RNUM; i++) { v[i] = expf(v[i] - mx); sum += v[i]; }
        float la = 0.f;
        const float inv = 1.f / sum;
#pragma unroll
        for (int i = 0; i < RNUM; i++) {
            v[i] *= inv; ssim[i] = v[i];
            la += v[i] * rlabel[b * RNUM + i];
        }
        s_lbl = la;
    }
    __syncthreads();
    const float* Yb = g_Y + (size_t)b * 4 * ZDIM;
    const float lagg = s_lbl;
    const size_t rb = (size_t)b * KP_P1;
    for (int z = threadIdx.x; z < ZDIM; z += blockDim.x) {
        const float Y0 = Yb[z], Y1 = Yb[ZDIM + z], Y2 = Yb[2 * ZDIM + z], Y3 = Yb[3 * ZDIM + z];
        float f[7];
        f[0] = fmaxf(0.5f * (Y0 + Y1), 0.f);
        f[1] = fmaxf(0.5f * (Y0 + Y2), 0.f);
        f[2] = fmaxf(0.5f * (Y0 + Y3), 0.f);
        float rv, rt;
        if (b != 0) {
            rv = fmaxf(Y2, 0.f);
            rt = fmaxf(Y1, 0.f);
        } else {
            rv = 0.f; rt = 0.f;
#pragma unroll
            for (int i = 0; i < RNUM; i++) {
                const float yp = g_Y[(size_t)(EDGE_ROWS + i) * ZDIM + z];
                rt += ssim[i] * fmaxf(0.5f * (Y1 + yp), 0.f);
                rv += ssim[i] * fmaxf(0.5f * (Y2 + yp), 0.f);
            }
        }
        f[3] = rv;
        f[4] = rt;
        f[5] = fmaxf(Y3, 0.f);
        f[6] = fmaxf(lagg * lbl_w[z] + lbl_b[z], 0.f);
#pragma unroll
        for (int s = 0; s < 7; s++)
            g_aF[rb + s * ZDIM + z] = __float2half_rn(f[s]);
    }
}

__global__ void final_out(const float* __restrict__ p3_w, const float* __restrict__ p3_b,
                          float* __restrict__ out) {
    const int warp = (blockIdx.x * blockDim.x + threadIdx.x) >> 5;
    const int lane = threadIdx.x & 31;
    if (warp >= BSZ) return;
    const float* h = g_h2 + (size_t)warp * H2D;
    float s = 0.f;
    for (int j = lane; j < H2D; j += 32) s += h[j] * p3_w[j];
#pragma unroll
    for (int off = 16; off; off >>= 1) s += __shfl_xor_sync(0xffffffffu, s, off);
    if (lane == 0) out[warp] = 1.f / (1.f + expf(-(s + p3_b[0])));
}

// ---------------- host launcher ----------------
extern "C" void kernel_launch(void* const* d_in, const int* in_sizes, int n_in,
                              void* d_out, int out_size) {
    const float* vis   = (const float*)d_in[0];
    const float* txt   = (const float*)d_in[1];
    const float* sim   = (const float*)d_in[2];
    const float* rvis  = (const float*)d_in[3];
    const float* rtxt  = (const float*)d_in[4];
    const float* rlbl  = (const float*)d_in[5];
    const float* usr   = (const float*)d_in[6];
    const float* rusr  = (const float*)d_in[7];
    const float* vis_w = (const float*)d_in[9],  *vis_b = (const float*)d_in[10];
    const float* txt_w = (const float*)d_in[11], *txt_b = (const float*)d_in[12];
    const float* usr_w = (const float*)d_in[13], *usr_b = (const float*)d_in[14];
    const float* rvis_w = (const float*)d_in[15], *rvis_b = (const float*)d_in[16];
    const float* rtxt_w = (const float*)d_in[17], *rtxt_b = (const float*)d_in[18];
    const float* rusr_w = (const float*)d_in[19], *rusr_b = (const float*)d_in[20];
    const float* hg_w  = (const float*)d_in[21], *hg_b = (const float*)d_in[22];
    const float* lbl_w = (const float*)d_in[23], *lbl_b = (const float*)d_in[24];
    const float* p1_w  = (const float*)d_in[25], *p1_b = (const float*)d_in[26];
    const float* p2_w  = (const float*)d_in[27], *p2_b = (const float*)d_in[28];
    const float* p3_w  = (const float*)d_in[29], *p3_b = (const float*)d_in[30];

    float *Y, *h2, *biasD, *Rout, *E;
    __half *aS, *aR, *wE, *aM, *wHg, *aF, *wP1, *aH1, *wP2;
    cudaGetSymbolAddress((void**)&Rout, g_Rout);
    cudaGetSymbolAddress((void**)&E, g_E);
    cudaGetSymbolAddress((void**)&Y, g_Y);
    cudaGetSymbolAddress((void**)&h2, g_h2);
    cudaGetSymbolAddress((void**)&biasD, g_bias);
    cudaGetSymbolAddress((void**)&aS, g_aS);
    cudaGetSymbolAddress((void**)&aR, g_aR);
    cudaGetSymbolAddress((void**)&wE, g_wE);
    cudaGetSymbolAddress((void**)&aM, g_aM);
    cudaGetSymbolAddress((void**)&wHg, g_wHg);
    cudaGetSymbolAddress((void**)&aF, g_aF);
    cudaGetSymbolAddress((void**)&wP1, g_wP1);
    cudaGetSymbolAddress((void**)&aH1, g_aH1);
    cudaGetSymbolAddress((void**)&wP2, g_wP2);

    cudaFuncSetAttribute(hgemm<1,0>, cudaFuncAttributeMaxDynamicSharedMemorySize, SMEM_BYTES);
    cudaFuncSetAttribute(hgemm<0,0>, cudaFuncAttributeMaxDynamicSharedMemorySize, SMEM_BYTES);
    cudaFuncSetAttribute(hgemm<2,1>, cudaFuncAttributeMaxDynamicSharedMemorySize, SMEM_BYTES);
    cudaFuncSetAttribute(hgemm<2,0>, cudaFuncAttributeMaxDynamicSharedMemorySize, SMEM_BYTES);

    const size_t aSz = (size_t)BSZ * FDIM, aRz = (size_t)NRET * FDIM;
    const size_t wEz = (size_t)512 * FDIM;

    auto run_group = [&](ConvTable& T) {
        long long total = 0;
        for (int i = 0; i < T.n; i++) {
            T.nG[i] = (long long)T.j[i].rp * (T.j[i].cp >> 3);
            total += T.nG[i];
        }
        for (int i = T.n; i < 12; i++) T.nG[i] = 0x7fffffffffffLL;
        conv_batch<<<(unsigned)((total + 255) / 256), 256>>>(T, total);
    };
    {   // group 1: all weights + 3 single-sample A tensors
        ConvTable T; T.n = 12;
        T.j[0] = {txt_w,  wE + 0 * wEz, PDIM, FDIM, 512, FDIM};
        T.j[1] = {vis_w,  wE + 1 * wEz, PDIM, FDIM, 512, FDIM};
        T.j[2] = {usr_w,  wE + 2 * wEz, PDIM, FDIM, 512, FDIM};
        T.j[3] = {rtxt_w, wE + 3 * wEz, PDIM, FDIM, 512, FDIM};
        T.j[4] = {rvis_w, wE + 4 * wEz, PDIM, FDIM, 512, FDIM};
        T.j[5] = {rusr_w, wE + 5 * wEz, PDIM, FDIM, 512, FDIM};
        T.j[6] = {hg_w, wHg, ZDIM, PDIM, 512, KP_HG};
        T.j[7] = {p1_w, wP1, H1D, FEATD, 1024, KP_P1};
        T.j[8] = {p2_w, wP2, H2D, H1D, 256, KP_P2};
        T.j[9]  = {txt, aS + 0 * aSz, BSZ, FDIM, BSZ, FDIM};
        T.j[10] = {vis, aS + 1 * aSz, BSZ, FDIM, BSZ, FDIM};
        T.j[11] = {usr, aS + 2 * aSz, BSZ, FDIM, BSZ, FDIM};
        run_group(T);
    }
    {   ConvTable T; T.n = 1; T.j[0] = {rtxt, aR + 0 * aRz, NRET, FDIM, NRET, FDIM}; run_group(T); }
    {   ConvTable T; T.n = 1; T.j[0] = {rvis, aR + 1 * aRz, NRET, FDIM, NRET, FDIM}; run_group(T); }
    {   ConvTable T; T.n = 1; T.j[0] = {rusr, aR + 2 * aRz, NRET, FDIM, NRET, FDIM}; run_group(T); }

    bias_pack<<<1, 1024>>>(txt_b, vis_b, usr_b, rtxt_b, rvis_b, rusr_b, hg_b, p1_b, p2_b);

    // ---- 1) embeddings (z=3 batched, block 128x256, fp16 single pass) ----
    hgemm<1,0><<<dim3(2, 32, 3), 256, SMEM_BYTES>>>(
        aS, aSz, wE, wEz,
        biasD, 512, E, (size_t)BSZ * PDIM, PDIM, BSZ, PDIM, FDIM);
    hgemm<1,0><<<dim3(2, 320, 3), 256, SMEM_BYTES>>>(
        aR, aRz, wE + 3 * wEz, wEz,
        biasD + 3 * 512, 512, Rout, (size_t)NRET * PDIM, PDIM, NRET, PDIM, FDIM);

    // ---- 2) means (+pair means) -> g_aM plane ----
    build_means_fused<<<(BSZ * (PDIM / 4) + 255) / 256, 256>>>();

    // ---- 3) hg projection -> g_Y fp32 ----
    hgemm<0,0><<<dim3(2, 129, 1), 256, SMEM_BYTES>>>(
        aM, 0, wHg, 0,
        biasD + 3072, 0, Y, 0, ZDIM, M_ROWS, ZDIM, KP_HG);

    // ---- 4) feature assembly -> g_aF plane ----
    build_feat<<<BSZ, 256>>>(sim, rlbl, lbl_w, lbl_b);

    // ---- 5) MLP head ----
    hgemm<2,1><<<dim3(4, 32, 1), 256, SMEM_BYTES>>>(
        aF, 0, wP1, 0,
        biasD + 3584, 0, aH1, 0, KP_P2, BSZ, H1D, KP_P1);
    hgemm<2,0><<<dim3(1, 32, 1), 256, SMEM_BYTES>>>(
        aH1, 0, wP2, 0,
        biasD + 4608, 0, h2, 0, H2D, BSZ, H2D, KP_P2);

    final_out<<<(BSZ * 32 + 255) / 256, 256>>>(p3_w, p3_b, (float*)d_out);
}

// round 16
// speedup vs baseline: 3.0271x; 1.6405x over previous
#include <cuda_runtime.h>
#include <cuda_fp16.h>
#include <cstdint>
#include <math.h>

#define BSZ 4096
#define FDIM 768
#define PDIM 500
#define ZDIM 300
#define RNUM 10
#define NRET (BSZ * RNUM)          // 40960
#define EDGE_ROWS (BSZ * 4)        // 16384
#define M_ROWS (EDGE_ROWS + RNUM)  // 16394
#define FEATD 2100
#define H1D 800
#define H2D 200

#define MROWS_P 16512              // 129*128
#define KP_HG 512
#define KP_P1 2112
#define KP_P2 800

// ---------------- scratch ----------------
__device__ __align__(16) __half g_Rout[3ull * NRET * PDIM];   // fp16 now
__device__ __align__(16) __half g_E[3ull * BSZ * PDIM];       // fp16 now
__device__ float g_Y[(size_t)M_ROWS * ZDIM];
__device__ float g_h2[(size_t)BSZ * H2D];
__device__ float g_bias[8192];
// [0..3072) 6x512 embed biases, [3072..3584) hg, [3584..4608) p1, [4608..4864) p2

// ---------------- fp16 planes (single, no split) ----------------
__device__ __align__(16) __half g_aS[3ull * BSZ * FDIM];
__device__ __align__(16) __half g_aR[3ull * NRET * FDIM];
__device__ __align__(16) __half g_wE[6ull * 512 * FDIM];
__device__ __align__(16) __half g_aM[(size_t)MROWS_P * KP_HG];
__device__ __align__(16) __half g_wHg[(size_t)512 * KP_HG];
__device__ __align__(16) __half g_aF[(size_t)BSZ * KP_P1];
__device__ __align__(16) __half g_wP1[(size_t)1024 * KP_P1];
__device__ __align__(16) __half g_aH1[(size_t)BSZ * KP_P2];
__device__ __align__(16) __half g_wP2[(size_t)256 * KP_P2];

// ---------------- helpers ----------------
__device__ __forceinline__ uint32_t smem_u32(const void* p) {
    uint32_t a;
    asm("{ .reg .u64 t; cvta.to.shared.u64 t, %1; cvt.u32.u64 %0, t; }" : "=r"(a) : "l"(p));
    return a;
}
__device__ __forceinline__ void ldsm4(uint32_t* r, uint32_t addr) {
    asm volatile("ldmatrix.sync.aligned.m8n8.x4.shared.b16 {%0,%1,%2,%3}, [%4];"
                 : "=r"(r[0]), "=r"(r[1]), "=r"(r[2]), "=r"(r[3]) : "r"(addr));
}
__device__ __forceinline__ void mma16816(float* d, const uint32_t* a, uint32_t b0, uint32_t b1) {
    asm volatile(
        "mma.sync.aligned.m16n8k16.row.col.f32.f16.f16.f32 "
        "{%0,%1,%2,%3}, {%4,%5,%6,%7}, {%8,%9}, {%0,%1,%2,%3};"
        : "+f"(d[0]), "+f"(d[1]), "+f"(d[2]), "+f"(d[3])
        : "r"(a[0]), "r"(a[1]), "r"(a[2]), "r"(a[3]), "r"(b0), "r"(b1));
}
__device__ __forceinline__ uint32_t swz(int row, int chunk) {
    return (uint32_t)(row * 64 + ((chunk ^ ((row >> 1) & 3)) << 4));
}
__device__ __forceinline__ void cpa16(uint32_t dst, const void* src) {
    asm volatile("cp.async.cg.shared.global [%0], [%1], 16;" :: "r"(dst), "l"(src));
}
__device__ __forceinline__ void cpa_commit() {
    asm volatile("cp.async.commit_group;" ::: "memory");
}
__device__ __forceinline__ uint16_t h2u(__half h) { return *reinterpret_cast<uint16_t*>(&h); }
__device__ __forceinline__ uint2 pack4h(const float* v) {
    __half h[4];
#pragma unroll
    for (int j = 0; j < 4; j++) h[j] = __float2half_rn(v[j]);
    uint2 o;
    o.x = ((uint32_t)h2u(h[1]) << 16) | h2u(h[0]);
    o.y = ((uint32_t)h2u(h[3]) << 16) | h2u(h[2]);
    return o;
}
__device__ __forceinline__ float4 load4h(const __half* p) {
    const uint2 u = *reinterpret_cast<const uint2*>(p);
    const __half2 a = *reinterpret_cast<const __half2*>(&u.x);
    const __half2 b = *reinterpret_cast<const __half2*>(&u.y);
    float4 o;
    o.x = __half2float(a.x); o.y = __half2float(a.y);
    o.z = __half2float(b.x); o.w = __half2float(b.y);
    return o;
}

#define STAGE_B 24576                 // A 8K | W 16K
#define SMEM_BYTES (4 * STAGE_B)      // 98304

// ============ fp16 HMMA GEMM: C = epi(A @ W^T + bias), single pass ============
// 512 threads / 16 warps, block 128x256, warp tile 32x64, 4-stage cp.async.
template <int EPI, int OUT>  // EPI: 0 none,1 tanh,2 relu ; OUT: 0 fp32, 1 fp16
__global__ void __launch_bounds__(512, 1)
hgemm(const __half* __restrict__ Ap, size_t aZ,
      const __half* __restrict__ Wp, size_t wZ,
      const float* __restrict__ bias, int bStride,
      void* __restrict__ Cp, size_t cZ, int ldC,
      int M, int N, int Kp) {
    extern __shared__ char smem[];
    const uint32_t sb = smem_u32(smem);
    const int tid = threadIdx.x, wid = tid >> 5, lane = tid & 31;
    const int bm = blockIdx.y * 128, bn = blockIdx.x * 256;
    const int z = blockIdx.z;
    const __half* Ab = Ap + (size_t)z * aZ;
    const __half* Wb = Wp + (size_t)z * wZ;
    const float* bb = bias + (size_t)z * bStride;
    const int wm = (wid & 3) * 32;   // 4 warps down M
    const int wn = (wid >> 2) * 64;  // 4 warps across N
    const int nch = Kp >> 5;

    float acc[16][4];
#pragma unroll
    for (int i = 0; i < 16; i++)
#pragma unroll
        for (int j = 0; j < 4; j++) acc[i][j] = 0.f;

    auto fill = [&](int c) {
        if (c >= nch) return;
        const int k0 = c << 5;
        const uint32_t st = sb + (uint32_t)(c & 3) * STAGE_B;
        {   // A: 512 granules, one per thread
            const int row = tid >> 2, ch = tid & 3;
            const uint32_t so = swz(row, ch);
            cpa16(st + so, Ab + (size_t)(bm + row) * Kp + k0 + ch * 8);
        }
#pragma unroll
        for (int i = 0; i < 2; i++) {  // W: 1024 granules, two per thread
            const int g = tid + (i << 9);
            const int row = g >> 2, ch = g & 3;
            const uint32_t so = swz(row, ch);
            cpa16(st + 8192 + so, Wb + (size_t)(bn + row) * Kp + k0 + ch * 8);
        }
    };

    fill(0); cpa_commit();
    fill(1); cpa_commit();
    fill(2); cpa_commit();

    for (int c = 0; c < nch; c++) {
        asm volatile("cp.async.wait_group 2;" ::: "memory");
        __syncthreads();
        fill(c + 3);
        cpa_commit();

        const uint32_t st = sb + (uint32_t)(c & 3) * STAGE_B;
        const uint32_t sA = st, sW = st + 8192;
#pragma unroll
        for (int ks = 0; ks < 2; ks++) {
            uint32_t ah[2][4];
#pragma unroll
            for (int mi = 0; mi < 2; mi++) {
                const int r = wm + mi * 16 + (lane & 15);
                const int cc = 2 * ks + (lane >> 4);
                ldsm4(ah[mi], sA + swz(r, cc));
            }
#pragma unroll
            for (int ng = 0; ng < 4; ng++) {
                const int r = wn + ng * 16 + ((lane >> 4) << 3) + (lane & 7);
                const int cc = 2 * ks + ((lane >> 3) & 1);
                uint32_t w[4];
                ldsm4(w, sW + swz(r, cc));
#pragma unroll
                for (int mi = 0; mi < 2; mi++)
#pragma unroll
                    for (int sub = 0; sub < 2; sub++)
                        mma16816(acc[mi * 8 + ng * 2 + sub], ah[mi], w[2 * sub], w[2 * sub + 1]);
            }
        }
    }

    // ---- epilogue: warp covers rows wm..wm+31, cols wn..wn+63 ----
#pragma unroll
    for (int mi = 0; mi < 2; mi++)
#pragma unroll
        for (int nj = 0; nj < 8; nj++) {
            const float* d = acc[mi * 8 + nj];
            const int gm = bm + wm + mi * 16 + (lane >> 2);
            const int gn = bn + wn + nj * 8 + (lane & 3) * 2;
            if (gn >= N) continue;
            const float b0 = bb[gn], b1 = bb[gn + 1];
#pragma unroll
            for (int half = 0; half < 2; half++) {
                const int gr = gm + half * 8;
                if (gr >= M) continue;
                float v0 = d[half * 2 + 0] + b0;
                float v1 = d[half * 2 + 1] + b1;
                if (EPI == 1) { v0 = tanhf(v0); v1 = tanhf(v1); }
                else if (EPI == 2) { v0 = fmaxf(v0, 0.f); v1 = fmaxf(v1, 0.f); }
                if (OUT == 0) {
                    float2 o; o.x = v0; o.y = v1;
                    *reinterpret_cast<float2*>((float*)Cp + (size_t)z * cZ + (size_t)gr * ldC + gn) = o;
                } else {
                    __half* Ch = (__half*)Cp + (size_t)z * cZ;
                    const __half h0 = __float2half_rn(v0), h1 = __float2half_rn(v1);
                    const uint32_t hp = ((uint32_t)h2u(h1) << 16) | h2u(h0);
                    *reinterpret_cast<uint32_t*>(Ch + (size_t)gr * ldC + gn) = hp;
                }
            }
        }
}

// ---------------- table-driven batched preconvert (fp32 -> fp16 plane) ----------------
struct ConvJob { const float* src; __half* dst; int rows, cols, rp, cp; };
struct ConvTable { ConvJob j[12]; long long nG[12]; int n; };

__global__ void conv_batch(ConvTable T, long long total) {
    long long g = (long long)blockIdx.x * blockDim.x + threadIdx.x;
    if (g >= total) return;
    int ji = 0;
    while (g >= T.nG[ji]) { g -= T.nG[ji]; ji++; }
    const ConvJob& J = T.j[ji];
    const int gpr = J.cp >> 3;
    const int row = (int)(g / gpr), c8 = (int)(g % gpr) * 8;
    float v[8];
    if (row < J.rows && c8 + 8 <= J.cols) {
        const float4 a = *reinterpret_cast<const float4*>(J.src + (size_t)row * J.cols + c8);
        const float4 b = *reinterpret_cast<const float4*>(J.src + (size_t)row * J.cols + c8 + 4);
        v[0] = a.x; v[1] = a.y; v[2] = a.z; v[3] = a.w;
        v[4] = b.x; v[5] = b.y; v[6] = b.z; v[7] = b.w;
    } else {
#pragma unroll
        for (int q = 0; q < 8; q++)
            v[q] = (row < J.rows && c8 + q < J.cols) ? J.src[(size_t)row * J.cols + c8 + q] : 0.f;
    }
    uint4 hi;
    __half* ph = reinterpret_cast<__half*>(&hi);
#pragma unroll
    for (int q = 0; q < 8; q++) ph[q] = __float2half_rn(v[q]);
    *reinterpret_cast<uint4*>(J.dst + (size_t)row * J.cp + c8) = hi;
}

__global__ void bias_pack(const float* b0, const float* b1, const float* b2,
                          const float* b3, const float* b4, const float* b5,
                          const float* bhg, const float* bp1, const float* bp2) {
    const int t = threadIdx.x;  // 1024
    if (t < 512) {
        g_bias[0 * 512 + t] = (t < PDIM) ? b0[t] : 0.f;
        g_bias[1 * 512 + t] = (t < PDIM) ? b1[t] : 0.f;
        g_bias[2 * 512 + t] = (t < PDIM) ? b2[t] : 0.f;
        g_bias[3 * 512 + t] = (t < PDIM) ? b3[t] : 0.f;
        g_bias[4 * 512 + t] = (t < PDIM) ? b4[t] : 0.f;
        g_bias[5 * 512 + t] = (t < PDIM) ? b5[t] : 0.f;
        g_bias[3072 + t] = (t < ZDIM) ? bhg[t] : 0.f;
    }
    g_bias[3584 + t] = (t < H1D) ? bp1[t] : 0.f;
    if (t < 256) g_bias[4608 + t] = (t < H2D) ? bp2[t] : 0.f;
}

// ---------------- fused retrieved-sum + edge-mean + pair-mean -> g_aM (fp16) ----------------
__global__ void build_means_fused() {
    const int idx = blockIdx.x * blockDim.x + threadIdx.x;
    if (idx >= BSZ * (PDIM / 4)) return;
    const int b = idx / (PDIM / 4), p4 = (idx % (PDIM / 4)) * 4;

    if (idx < RNUM * (PDIM / 4)) {  // pair means (10 rows, sample-0)
        const int i = idx / (PDIM / 4);
        const int q4 = (idx % (PDIM / 4)) * 4;
        const float4 a = load4h(g_Rout + (size_t)0 * NRET * PDIM + (size_t)i * PDIM + q4);
        const float4 c = load4h(g_Rout + (size_t)1 * NRET * PDIM + (size_t)i * PDIM + q4);
        float v[4] = {0.5f * (a.x + c.x), 0.5f * (a.y + c.y), 0.5f * (a.z + c.z), 0.5f * (a.w + c.w)};
        *reinterpret_cast<uint2*>(g_aM + (size_t)(EDGE_ROWS + i) * KP_HG + q4) = pack4h(v);
    }

    const float4 et = load4h(g_E + ((size_t)0 * BSZ + b) * PDIM + p4);
    const float4 ev = load4h(g_E + ((size_t)1 * BSZ + b) * PDIM + p4);
    const float4 eu = load4h(g_E + ((size_t)2 * BSZ + b) * PDIM + p4);

    float4 S[3];
#pragma unroll
    for (int s = 0; s < 3; s++) {
        const __half* base = g_Rout + (size_t)s * NRET * PDIM + (size_t)b * RNUM * PDIM + p4;
        float4 a = make_float4(0.f, 0.f, 0.f, 0.f);
#pragma unroll
        for (int i = 0; i < RNUM; i++) {
            const float4 v = load4h(base + (size_t)i * PDIM);
            a.x += v.x; a.y += v.y; a.z += v.z; a.w += v.w;
        }
        S[s] = a;
    }
    const float i3 = 1.f / 3.f, i11 = 1.f / 11.f;
    float o[4][4];
    o[0][0] = (et.x + ev.x + eu.x) * i3; o[0][1] = (et.y + ev.y + eu.y) * i3;
    o[0][2] = (et.z + ev.z + eu.z) * i3; o[0][3] = (et.w + ev.w + eu.w) * i3;
    o[1][0] = (S[0].x + et.x) * i11; o[1][1] = (S[0].y + et.y) * i11;
    o[1][2] = (S[0].z + et.z) * i11; o[1][3] = (S[0].w + et.w) * i11;
    o[2][0] = (S[1].x + ev.x) * i11; o[2][1] = (S[1].y + ev.y) * i11;
    o[2][2] = (S[1].z + ev.z) * i11; o[2][3] = (S[1].w + ev.w) * i11;
    o[3][0] = (S[2].x + eu.x) * i11; o[3][1] = (S[2].y + eu.y) * i11;
    o[3][2] = (S[2].z + eu.z) * i11; o[3][3] = (S[2].w + eu.w) * i11;
#pragma unroll
    for (int e = 0; e < 4; e++)
        *reinterpret_cast<uint2*>(g_aM + (size_t)(b * 4 + e) * KP_HG + p4) = pack4h(o[e]);
}

// ---------------- feature assembly -> g_aF (fp16) ----------------
__global__ void build_feat(const float* __restrict__ similarity,
                           const float* __restrict__ rlabel,
                           const float* __restrict__ lbl_w,
                           const float* __restrict__ lbl_b) {
    const int b = blockIdx.x;
    __shared__ float ssim[RNUM];
    __shared__ float s_lbl;
    if (threadIdx.x == 0) {
        float v[RNUM], mx = -1e30f;
#pragma unroll
        for (int i = 0; i < RNUM; i++) { v[i] = similarity[b * RNUM + i]; mx = fmaxf(mx, v[i]); }
        float sum = 0.f;
#pragma unroll
        for (int i = 0; i < RNUM; i++) { v[i] = expf(v[i] - mx); sum += v[i]; }
        float la = 0.f;
        const float inv = 1.f / sum;
#pragma unroll
        for (int i = 0; i < RNUM; i++) {
            v[i] *= inv; ssim[i] = v[i];
            la += v[i] * rlabel[b * RNUM + i];
        }
        s_lbl = la;
    }
    __syncthreads();
    const float* Yb = g_Y + (size_t)b * 4 * ZDIM;
    const float lagg = s_lbl;
    const size_t rb = (size_t)b * KP_P1;
    for (int z = threadIdx.x; z < ZDIM; z += blockDim.x) {
        const float Y0 = Yb[z], Y1 = Yb[ZDIM + z], Y2 = Yb[2 * ZDIM + z], Y3 = Yb[3 * ZDIM + z];
        float f[7];
        f[0] = fmaxf(0.5f * (Y0 + Y1), 0.f);
        f[1] = fmaxf(0.5f * (Y0 + Y2), 0.f);
        f[2] = fmaxf(0.5f * (Y0 + Y3), 0.f);
        float rv, rt;
        if (b != 0) {
            rv = fmaxf(Y2, 0.f);
            rt = fmaxf(Y1, 0.f);
        } else {
            rv = 0.f; rt = 0.f;
#pragma unroll
            for (int i = 0; i < RNUM; i++) {
                const float yp = g_Y[(size_t)(EDGE_ROWS + i) * ZDIM + z];
                rt += ssim[i] * fmaxf(0.5f * (Y1 + yp), 0.f);
                rv += ssim[i] * fmaxf(0.5f * (Y2 + yp), 0.f);
            }
        }
        f[3] = rv;
        f[4] = rt;
        f[5] = fmaxf(Y3, 0.f);
        f[6] = fmaxf(lagg * lbl_w[z] + lbl_b[z], 0.f);
#pragma unroll
        for (int s = 0; s < 7; s++)
            g_aF[rb + s * ZDIM + z] = __float2half_rn(f[s]);
    }
}

__global__ void final_out(const float* __restrict__ p3_w, const float* __restrict__ p3_b,
                          float* __restrict__ out) {
    const int warp = (blockIdx.x * blockDim.x + threadIdx.x) >> 5;
    const int lane = threadIdx.x & 31;
    if (warp >= BSZ) return;
    const float* h = g_h2 + (size_t)warp * H2D;
    float s = 0.f;
    for (int j = lane; j < H2D; j += 32) s += h[j] * p3_w[j];
#pragma unroll
    for (int off = 16; off; off >>= 1) s += __shfl_xor_sync(0xffffffffu, s, off);
    if (lane == 0) out[warp] = 1.f / (1.f + expf(-(s + p3_b[0])));
}

// ---------------- host launcher ----------------
extern "C" void kernel_launch(void* const* d_in, const int* in_sizes, int n_in,
                              void* d_out, int out_size) {
    const float* vis   = (const float*)d_in[0];
    const float* txt   = (const float*)d_in[1];
    const float* sim   = (const float*)d_in[2];
    const float* rvis  = (const float*)d_in[3];
    const float* rtxt  = (const float*)d_in[4];
    const float* rlbl  = (const float*)d_in[5];
    const float* usr   = (const float*)d_in[6];
    const float* rusr  = (const float*)d_in[7];
    const float* vis_w = (const float*)d_in[9],  *vis_b = (const float*)d_in[10];
    const float* txt_w = (const float*)d_in[11], *txt_b = (const float*)d_in[12];
    const float* usr_w = (const float*)d_in[13], *usr_b = (const float*)d_in[14];
    const float* rvis_w = (const float*)d_in[15], *rvis_b = (const float*)d_in[16];
    const float* rtxt_w = (const float*)d_in[17], *rtxt_b = (const float*)d_in[18];
    const float* rusr_w = (const float*)d_in[19], *rusr_b = (const float*)d_in[20];
    const float* hg_w  = (const float*)d_in[21], *hg_b = (const float*)d_in[22];
    const float* lbl_w = (const float*)d_in[23], *lbl_b = (const float*)d_in[24];
    const float* p1_w  = (const float*)d_in[25], *p1_b = (const float*)d_in[26];
    const float* p2_w  = (const float*)d_in[27], *p2_b = (const float*)d_in[28];
    const float* p3_w  = (const float*)d_in[29], *p3_b = (const float*)d_in[30];

    float *Y, *h2, *biasD;
    __half *Rout, *E, *aS, *aR, *wE, *aM, *wHg, *aF, *wP1, *aH1, *wP2;
    cudaGetSymbolAddress((void**)&Rout, g_Rout);
    cudaGetSymbolAddress((void**)&E, g_E);
    cudaGetSymbolAddress((void**)&Y, g_Y);
    cudaGetSymbolAddress((void**)&h2, g_h2);
    cudaGetSymbolAddress((void**)&biasD, g_bias);
    cudaGetSymbolAddress((void**)&aS, g_aS);
    cudaGetSymbolAddress((void**)&aR, g_aR);
    cudaGetSymbolAddress((void**)&wE, g_wE);
    cudaGetSymbolAddress((void**)&aM, g_aM);
    cudaGetSymbolAddress((void**)&wHg, g_wHg);
    cudaGetSymbolAddress((void**)&aF, g_aF);
    cudaGetSymbolAddress((void**)&wP1, g_wP1);
    cudaGetSymbolAddress((void**)&aH1, g_aH1);
    cudaGetSymbolAddress((void**)&wP2, g_wP2);

    cudaFuncSetAttribute(hgemm<1,1>, cudaFuncAttributeMaxDynamicSharedMemorySize, SMEM_BYTES);
    cudaFuncSetAttribute(hgemm<0,0>, cudaFuncAttributeMaxDynamicSharedMemorySize, SMEM_BYTES);
    cudaFuncSetAttribute(hgemm<2,1>, cudaFuncAttributeMaxDynamicSharedMemorySize, SMEM_BYTES);
    cudaFuncSetAttribute(hgemm<2,0>, cudaFuncAttributeMaxDynamicSharedMemorySize, SMEM_BYTES);

    const size_t aSz = (size_t)BSZ * FDIM, aRz = (size_t)NRET * FDIM;
    const size_t wEz = (size_t)512 * FDIM;

    auto run_group = [&](ConvTable& T) {
        long long total = 0;
        for (int i = 0; i < T.n; i++) {
            T.nG[i] = (long long)T.j[i].rp * (T.j[i].cp >> 3);
            total += T.nG[i];
        }
        for (int i = T.n; i < 12; i++) T.nG[i] = 0x7fffffffffffLL;
        conv_batch<<<(unsigned)((total + 255) / 256), 256>>>(T, total);
    };
    {   // group 1: all weights + 3 single-sample A tensors
        ConvTable T; T.n = 12;
        T.j[0] = {txt_w,  wE + 0 * wEz, PDIM, FDIM, 512, FDIM};
        T.j[1] = {vis_w,  wE + 1 * wEz, PDIM, FDIM, 512, FDIM};
        T.j[2] = {usr_w,  wE + 2 * wEz, PDIM, FDIM, 512, FDIM};
        T.j[3] = {rtxt_w, wE + 3 * wEz, PDIM, FDIM, 512, FDIM};
        T.j[4] = {rvis_w, wE + 4 * wEz, PDIM, FDIM, 512, FDIM};
        T.j[5] = {rusr_w, wE + 5 * wEz, PDIM, FDIM, 512, FDIM};
        T.j[6] = {hg_w, wHg, ZDIM, PDIM, 512, KP_HG};
        T.j[7] = {p1_w, wP1, H1D, FEATD, 1024, KP_P1};
        T.j[8] = {p2_w, wP2, H2D, H1D, 256, KP_P2};
        T.j[9]  = {txt, aS + 0 * aSz, BSZ, FDIM, BSZ, FDIM};
        T.j[10] = {vis, aS + 1 * aSz, BSZ, FDIM, BSZ, FDIM};
        T.j[11] = {usr, aS + 2 * aSz, BSZ, FDIM, BSZ, FDIM};
        run_group(T);
    }
    {   ConvTable T; T.n = 1; T.j[0] = {rtxt, aR + 0 * aRz, NRET, FDIM, NRET, FDIM}; run_group(T); }
    {   ConvTable T; T.n = 1; T.j[0] = {rvis, aR + 1 * aRz, NRET, FDIM, NRET, FDIM}; run_group(T); }
    {   ConvTable T; T.n = 1; T.j[0] = {rusr, aR + 2 * aRz, NRET, FDIM, NRET, FDIM}; run_group(T); }

    bias_pack<<<1, 1024>>>(txt_b, vis_b, usr_b, rtxt_b, rvis_b, rusr_b, hg_b, p1_b, p2_b);

    // ---- 1) embeddings (z=3 batched, 16 warps, fp16 in/out) ----
    hgemm<1,1><<<dim3(2, 32, 3), 512, SMEM_BYTES>>>(
        aS, aSz, wE, wEz,
        biasD, 512, E, (size_t)BSZ * PDIM, PDIM, BSZ, PDIM, FDIM);
    hgemm<1,1><<<dim3(2, 320, 3), 512, SMEM_BYTES>>>(
        aR, aRz, wE + 3 * wEz, wEz,
        biasD + 3 * 512, 512, Rout, (size_t)NRET * PDIM, PDIM, NRET, PDIM, FDIM);

    // ---- 2) means (+pair means) -> g_aM plane ----
    build_means_fused<<<(BSZ * (PDIM / 4) + 255) / 256, 256>>>();

    // ---- 3) hg projection -> g_Y fp32 ----
    hgemm<0,0><<<dim3(2, 129, 1), 512, SMEM_BYTES>>>(
        aM, 0, wHg, 0,
        biasD + 3072, 0, Y, 0, ZDIM, M_ROWS, ZDIM, KP_HG);

    // ---- 4) feature assembly -> g_aF plane ----
    build_feat<<<BSZ, 256>>>(sim, rlbl, lbl_w, lbl_b);

    // ---- 5) MLP head ----
    hgemm<2,1><<<dim3(4, 32, 1), 512, SMEM_BYTES>>>(
        aF, 0, wP1, 0,
        biasD + 3584, 0, aH1, 0, KP_P2, BSZ, H1D, KP_P1);
    hgemm<2,0><<<dim3(1, 32, 1), 512, SMEM_BYTES>>>(
        aH1, 0, wP2, 0,
        biasD + 4608, 0, h2, 0, H2D, BSZ, H2D, KP_P2);

    final_out<<<(BSZ * 32 + 255) / 256, 256>>>(p3_w, p3_b, (float*)d_out);
}

// round 17
// speedup vs baseline: 3.1401x; 1.0373x over previous
#include <cuda_runtime.h>
#include <cuda_fp16.h>
#include <cstdint>
#include <math.h>

#define BSZ 4096
#define FDIM 768
#define PDIM 500
#define ZDIM 300
#define RNUM 10
#define NRET (BSZ * RNUM)          // 40960
#define EDGE_ROWS (BSZ * 4)        // 16384
#define M_ROWS (EDGE_ROWS + RNUM)  // 16394
#define FEATD 2100
#define H1D 800
#define H2D 200

#define MROWS_P 16512              // 129*128
#define KP_HG 512
#define KP_P1 2112
#define KP_P2 832                  // 800 padded to 13*64

// ---------------- scratch ----------------
__device__ __align__(16) __half g_Rout[3ull * NRET * PDIM];
__device__ __align__(16) __half g_E[3ull * BSZ * PDIM];
__device__ float g_Y[(size_t)M_ROWS * ZDIM];
__device__ float g_h2[(size_t)BSZ * H2D];
__device__ float g_bias[8192];
// [0..3072) 6x512 embed biases, [3072..3584) hg, [3584..4608) p1, [4608..4864) p2

// ---------------- fp16 planes ----------------
__device__ __align__(16) __half g_aS[3ull * BSZ * FDIM];
__device__ __align__(16) __half g_aR[3ull * NRET * FDIM];
__device__ __align__(16) __half g_wE[6ull * 512 * FDIM];
__device__ __align__(16) __half g_aM[(size_t)MROWS_P * KP_HG];
__device__ __align__(16) __half g_wHg[(size_t)512 * KP_HG];
__device__ __align__(16) __half g_aF[(size_t)BSZ * KP_P1];
__device__ __align__(16) __half g_wP1[(size_t)1024 * KP_P1];
__device__ __align__(16) __half g_aH1[(size_t)BSZ * KP_P2];   // p1 out; cols 800..831 stay zero
__device__ __align__(16) __half g_wP2[(size_t)256 * KP_P2];

// ---------------- helpers ----------------
__device__ __forceinline__ uint32_t smem_u32(const void* p) {
    uint32_t a;
    asm("{ .reg .u64 t; cvta.to.shared.u64 t, %1; cvt.u32.u64 %0, t; }" : "=r"(a) : "l"(p));
    return a;
}
__device__ __forceinline__ void ldsm4(uint32_t* r, uint32_t addr) {
    asm volatile("ldmatrix.sync.aligned.m8n8.x4.shared.b16 {%0,%1,%2,%3}, [%4];"
                 : "=r"(r[0]), "=r"(r[1]), "=r"(r[2]), "=r"(r[3]) : "r"(addr));
}
__device__ __forceinline__ void mma16816(float* d, const uint32_t* a, uint32_t b0, uint32_t b1) {
    asm volatile(
        "mma.sync.aligned.m16n8k16.row.col.f32.f16.f16.f32 "
        "{%0,%1,%2,%3}, {%4,%5,%6,%7}, {%8,%9}, {%0,%1,%2,%3};"
        : "+f"(d[0]), "+f"(d[1]), "+f"(d[2]), "+f"(d[3])
        : "r"(a[0]), "r"(a[1]), "r"(a[2]), "r"(a[3]), "r"(b0), "r"(b1));
}
__device__ __forceinline__ uint32_t swz(int row, int chunk) {
    return (uint32_t)(row * 64 + ((chunk ^ ((row >> 1) & 3)) << 4));
}
__device__ __forceinline__ void cpa16(uint32_t dst, const void* src) {
    asm volatile("cp.async.cg.shared.global [%0], [%1], 16;" :: "r"(dst), "l"(src));
}
__device__ __forceinline__ void cpa_commit() {
    asm volatile("cp.async.commit_group;" ::: "memory");
}
__device__ __forceinline__ uint16_t h2u(__half h) { return *reinterpret_cast<uint16_t*>(&h); }
__device__ __forceinline__ uint2 pack4h(const float* v) {
    __half h[4];
#pragma unroll
    for (int j = 0; j < 4; j++) h[j] = __float2half_rn(v[j]);
    uint2 o;
    o.x = ((uint32_t)h2u(h[1]) << 16) | h2u(h[0]);
    o.y = ((uint32_t)h2u(h[3]) << 16) | h2u(h[2]);
    return o;
}
__device__ __forceinline__ float4 load4h(const __half* p) {
    const uint2 u = *reinterpret_cast<const uint2*>(p);
    const __half2 a = *reinterpret_cast<const __half2*>(&u.x);
    const __half2 b = *reinterpret_cast<const __half2*>(&u.y);
    float4 o;
    o.x = __half2float(a.x); o.y = __half2float(a.y);
    o.z = __half2float(b.x); o.w = __half2float(b.y);
    return o;
}

// stage = 64-wide K chunk: A0 8K | A1 8K | W0 16K | W1 16K
#define STAGE_B 49152
#define SMEM_BYTES (4 * STAGE_B)      // 196608

// ============ fp16 HMMA GEMM: C = epi(A @ W^T + bias) ============
// 512 thr / 16 warps, block 128x256, warp 32x64, 4-stage x 64-K cp.async pipeline.
// MODE 0: generic. MODE 1: fused embeds z=0..5 (3 singles + 3 retrieved), fp16 out, tanh.
template <int EPI, int OUT, int MODE>
__global__ void __launch_bounds__(512, 1)
hgemm(const __half* __restrict__ Ap, size_t aZ,
      const __half* __restrict__ Wp, size_t wZ,
      const float* __restrict__ bias, int bStride,
      void* __restrict__ Cp, size_t cZ, int ldC,
      int M, int N, int Kp) {
    const __half *Ab, *Wb;
    const float* bb;
    void* Cb;
    if (MODE == 1) {
        const int z = blockIdx.z;
        const bool single = z < 3;
        M = single ? BSZ : NRET;
        if (blockIdx.y * 128 >= M) return;
        Ab = single ? g_aS + (size_t)z * ((size_t)BSZ * FDIM)
                    : g_aR + (size_t)(z - 3) * ((size_t)NRET * FDIM);
        Wb = g_wE + (size_t)z * ((size_t)512 * FDIM);
        bb = g_bias + z * 512;
        Cb = single ? (void*)(g_E + (size_t)z * BSZ * PDIM)
                    : (void*)(g_Rout + (size_t)(z - 3) * NRET * PDIM);
        N = PDIM; Kp = FDIM; ldC = PDIM;
    } else {
        const int z = blockIdx.z;
        Ab = Ap + (size_t)z * aZ;
        Wb = Wp + (size_t)z * wZ;
        bb = bias + (size_t)z * bStride;
        Cb = (OUT == 0) ? (void*)((float*)Cp + (size_t)z * cZ)
                        : (void*)((__half*)Cp + (size_t)z * cZ);
    }

    extern __shared__ char smem[];
    const uint32_t sb = smem_u32(smem);
    const int tid = threadIdx.x, wid = tid >> 5, lane = tid & 31;
    const int bm = blockIdx.y * 128, bn = blockIdx.x * 256;
    const int wm = (wid & 3) * 32;   // 4 warps down M
    const int wn = (wid >> 2) * 64;  // 4 warps across N
    const int nch = Kp >> 6;         // 64-wide chunks

    float acc[16][4];
#pragma unroll
    for (int i = 0; i < 16; i++)
#pragma unroll
        for (int j = 0; j < 4; j++) acc[i][j] = 0.f;

    const int frow = tid >> 2, fch = tid & 3;       // A granule coords (512/subchunk)
    const uint32_t fso = swz(frow, fch);
    auto fill = [&](int c) {
        if (c >= nch) return;
        const int k0 = c << 6;
        const uint32_t st = sb + (uint32_t)(c & 3) * STAGE_B;
#pragma unroll
        for (int sub = 0; sub < 2; sub++) {  // A: 512 granules per 32-k subchunk
            const size_t off = (size_t)(bm + frow) * Kp + k0 + sub * 32 + fch * 8;
            cpa16(st + sub * 8192 + fso, Ab + off);
        }
#pragma unroll
        for (int i = 0; i < 4; i++) {        // W: 1024 granules per subchunk, 2 iters each
            const int sub = i >> 1;
            const int g = tid + ((i & 1) << 9);
            const int row = g >> 2, ch = g & 3;
            const size_t off = (size_t)(bn + row) * Kp + k0 + sub * 32 + ch * 8;
            cpa16(st + 16384 + sub * 16384 + swz(row, ch), Wb + off);
        }
    };

    fill(0); cpa_commit();
    fill(1); cpa_commit();
    fill(2); cpa_commit();

    for (int c = 0; c < nch; c++) {
        asm volatile("cp.async.wait_group 2;" ::: "memory");
        __syncthreads();
        fill(c + 3);
        cpa_commit();

        const uint32_t st = sb + (uint32_t)(c & 3) * STAGE_B;
#pragma unroll
        for (int ks = 0; ks < 4; ks++) {
            const int sub = ks >> 1, ksl = ks & 1;
            const uint32_t sA = st + sub * 8192;
            const uint32_t sW = st + 16384 + sub * 16384;
            uint32_t ah[2][4];
#pragma unroll
            for (int mi = 0; mi < 2; mi++) {
                const int r = wm + mi * 16 + (lane & 15);
                const int cc = 2 * ksl + (lane >> 4);
                ldsm4(ah[mi], sA + swz(r, cc));
            }
#pragma unroll
            for (int ng = 0; ng < 4; ng++) {
                const int r = wn + ng * 16 + ((lane >> 4) << 3) + (lane & 7);
                const int cc = 2 * ksl + ((lane >> 3) & 1);
                uint32_t w[4];
                ldsm4(w, sW + swz(r, cc));
#pragma unroll
                for (int mi = 0; mi < 2; mi++)
#pragma unroll
                    for (int sub2 = 0; sub2 < 2; sub2++)
                        mma16816(acc[mi * 8 + ng * 2 + sub2], ah[mi], w[2 * sub2], w[2 * sub2 + 1]);
            }
        }
    }

    // ---- epilogue ----
#pragma unroll
    for (int mi = 0; mi < 2; mi++)
#pragma unroll
        for (int nj = 0; nj < 8; nj++) {
            const float* d = acc[mi * 8 + nj];
            const int gm = bm + wm + mi * 16 + (lane >> 2);
            const int gn = bn + wn + nj * 8 + (lane & 3) * 2;
            if (gn >= N) continue;
            const float b0 = bb[gn], b1 = bb[gn + 1];
#pragma unroll
            for (int half = 0; half < 2; half++) {
                const int gr = gm + half * 8;
                if (gr >= M) continue;
                float v0 = d[half * 2 + 0] + b0;
                float v1 = d[half * 2 + 1] + b1;
                if (EPI == 1) { v0 = tanhf(v0); v1 = tanhf(v1); }
                else if (EPI == 2) { v0 = fmaxf(v0, 0.f); v1 = fmaxf(v1, 0.f); }
                if (OUT == 0) {
                    float2 o; o.x = v0; o.y = v1;
                    *reinterpret_cast<float2*>((float*)Cb + (size_t)gr * ldC + gn) = o;
                } else {
                    const __half h0 = __float2half_rn(v0), h1 = __float2half_rn(v1);
                    const uint32_t hp = ((uint32_t)h2u(h1) << 16) | h2u(h0);
                    *reinterpret_cast<uint32_t*>((__half*)Cb + (size_t)gr * ldC + gn) = hp;
                }
            }
        }
}

// ---------------- single-launch batched preconvert (fp32 -> fp16 plane) ----------------
struct ConvJob { const float* src; __half* dst; int rows, cols, rp, cp; };
struct ConvTable { ConvJob j[15]; long long nG[15]; int n; };

__global__ void conv_batch(ConvTable T, long long total) {
    long long g = (long long)blockIdx.x * blockDim.x + threadIdx.x;
    if (g >= total) return;
    int ji = 0;
    while (g >= T.nG[ji]) { g -= T.nG[ji]; ji++; }
    const ConvJob& J = T.j[ji];
    const int gpr = J.cp >> 3;
    const int row = (int)(g / gpr), c8 = (int)(g % gpr) * 8;
    float v[8];
    if (row < J.rows && c8 + 8 <= J.cols) {
        const float4 a = *reinterpret_cast<const float4*>(J.src + (size_t)row * J.cols + c8);
        const float4 b = *reinterpret_cast<const float4*>(J.src + (size_t)row * J.cols + c8 + 4);
        v[0] = a.x; v[1] = a.y; v[2] = a.z; v[3] = a.w;
        v[4] = b.x; v[5] = b.y; v[6] = b.z; v[7] = b.w;
    } else {
#pragma unroll
        for (int q = 0; q < 8; q++)
            v[q] = (row < J.rows && c8 + q < J.cols) ? J.src[(size_t)row * J.cols + c8 + q] : 0.f;
    }
    uint4 hi;
    __half* ph = reinterpret_cast<__half*>(&hi);
#pragma unroll
    for (int q = 0; q < 8; q++) ph[q] = __float2half_rn(v[q]);
    *reinterpret_cast<uint4*>(J.dst + (size_t)row * J.cp + c8) = hi;
}

__global__ void bias_pack(const float* b0, const float* b1, const float* b2,
                          const float* b3, const float* b4, const float* b5,
                          const float* bhg, const float* bp1, const float* bp2) {
    const int t = threadIdx.x;  // 1024
    if (t < 512) {
        g_bias[0 * 512 + t] = (t < PDIM) ? b0[t] : 0.f;
        g_bias[1 * 512 + t] = (t < PDIM) ? b1[t] : 0.f;
        g_bias[2 * 512 + t] = (t < PDIM) ? b2[t] : 0.f;
        g_bias[3 * 512 + t] = (t < PDIM) ? b3[t] : 0.f;
        g_bias[4 * 512 + t] = (t < PDIM) ? b4[t] : 0.f;
        g_bias[5 * 512 + t] = (t < PDIM) ? b5[t] : 0.f;
        g_bias[3072 + t] = (t < ZDIM) ? bhg[t] : 0.f;
    }
    g_bias[3584 + t] = (t < H1D) ? bp1[t] : 0.f;
    if (t < 256) g_bias[4608 + t] = (t < H2D) ? bp2[t] : 0.f;
}

// ---------------- fused retrieved-sum + edge-mean + pair-mean -> g_aM (fp16) ----------------
__global__ void build_means_fused() {
    const int idx = blockIdx.x * blockDim.x + threadIdx.x;
    if (idx >= BSZ * (PDIM / 4)) return;
    const int b = idx / (PDIM / 4), p4 = (idx % (PDIM / 4)) * 4;

    if (idx < RNUM * (PDIM / 4)) {  // pair means (10 rows, sample-0)
        const int i = idx / (PDIM / 4);
        const int q4 = (idx % (PDIM / 4)) * 4;
        const float4 a = load4h(g_Rout + (size_t)0 * NRET * PDIM + (size_t)i * PDIM + q4);
        const float4 c = load4h(g_Rout + (size_t)1 * NRET * PDIM + (size_t)i * PDIM + q4);
        float v[4] = {0.5f * (a.x + c.x), 0.5f * (a.y + c.y), 0.5f * (a.z + c.z), 0.5f * (a.w + c.w)};
        *reinterpret_cast<uint2*>(g_aM + (size_t)(EDGE_ROWS + i) * KP_HG + q4) = pack4h(v);
    }

    const float4 et = load4h(g_E + ((size_t)0 * BSZ + b) * PDIM + p4);
    const float4 ev = load4h(g_E + ((size_t)1 * BSZ + b) * PDIM + p4);
    const float4 eu = load4h(g_E + ((size_t)2 * BSZ + b) * PDIM + p4);

    float4 S[3];
#pragma unroll
    for (int s = 0; s < 3; s++) {
        const __half* base = g_Rout + (size_t)s * NRET * PDIM + (size_t)b * RNUM * PDIM + p4;
        float4 a = make_float4(0.f, 0.f, 0.f, 0.f);
#pragma unroll
        for (int i = 0; i < RNUM; i++) {
            const float4 v = load4h(base + (size_t)i * PDIM);
            a.x += v.x; a.y += v.y; a.z += v.z; a.w += v.w;
        }
        S[s] = a;
    }
    const float i3 = 1.f / 3.f, i11 = 1.f / 11.f;
    float o[4][4];
    o[0][0] = (et.x + ev.x + eu.x) * i3; o[0][1] = (et.y + ev.y + eu.y) * i3;
    o[0][2] = (et.z + ev.z + eu.z) * i3; o[0][3] = (et.w + ev.w + eu.w) * i3;
    o[1][0] = (S[0].x + et.x) * i11; o[1][1] = (S[0].y + et.y) * i11;
    o[1][2] = (S[0].z + et.z) * i11; o[1][3] = (S[0].w + et.w) * i11;
    o[2][0] = (S[1].x + ev.x) * i11; o[2][1] = (S[1].y + ev.y) * i11;
    o[2][2] = (S[1].z + ev.z) * i11; o[2][3] = (S[1].w + ev.w) * i11;
    o[3][0] = (S[2].x + eu.x) * i11; o[3][1] = (S[2].y + eu.y) * i11;
    o[3][2] = (S[2].z + eu.z) * i11; o[3][3] = (S[2].w + eu.w) * i11;
#pragma unroll
    for (int e = 0; e < 4; e++)
        *reinterpret_cast<uint2*>(g_aM + (size_t)(b * 4 + e) * KP_HG + p4) = pack4h(o[e]);
}

// ---------------- feature assembly -> g_aF (fp16) ----------------
__global__ void build_feat(const float* __restrict__ similarity,
                           const float* __restrict__ rlabel,
                           const float* __restrict__ lbl_w,
                           const float* __restrict__ lbl_b) {
    const int b = blockIdx.x;
    __shared__ float ssim[RNUM];
    __shared__ float s_lbl;
    if (threadIdx.x == 0) {
        float v[RNUM], mx = -1e30f;
#pragma unroll
        for (int i = 0; i < RNUM; i++) { v[i] = similarity[b * RNUM + i]; mx = fmaxf(mx, v[i]); }
        float sum = 0.f;
#pragma unroll
        for (int i = 0; i < RNUM; i++) { v[i] = expf(v[i] - mx); sum += v[i]; }
        float la = 0.f;
        const float inv = 1.f / sum;
#pragma unroll
        for (int i = 0; i < RNUM; i++) {
            v[i] *= inv; ssim[i] = v[i];
            la += v[i] * rlabel[b * RNUM + i];
        }
        s_lbl = la;
    }
    __syncthreads();
    const float* Yb = g_Y + (size_t)b * 4 * ZDIM;
    const float lagg = s_lbl;
    const size_t rb = (size_t)b * KP_P1;
    for (int z = threadIdx.x; z < ZDIM; z += blockDim.x) {
        const float Y0 = Yb[z], Y1 = Yb[ZDIM + z], Y2 = Yb[2 * ZDIM + z], Y3 = Yb[3 * ZDIM + z];
        float f[7];
        f[0] = fmaxf(0.5f * (Y0 + Y1), 0.f);
        f[1] = fmaxf(0.5f * (Y0 + Y2), 0.f);
        f[2] = fmaxf(0.5f * (Y0 + Y3), 0.f);
        float rv, rt;
        if (b != 0) {
            rv = fmaxf(Y2, 0.f);
            rt = fmaxf(Y1, 0.f);
        } else {
            rv = 0.f; rt = 0.f;
#pragma unroll
            for (int i = 0; i < RNUM; i++) {
                const float yp = g_Y[(size_t)(EDGE_ROWS + i) * ZDIM + z];
                rt += ssim[i] * fmaxf(0.5f * (Y1 + yp), 0.f);
                rv += ssim[i] * fmaxf(0.5f * (Y2 + yp), 0.f);
            }
        }
        f[3] = rv;
        f[4] = rt;
        f[5] = fmaxf(Y3, 0.f);
        f[6] = fmaxf(lagg * lbl_w[z] + lbl_b[z], 0.f);
#pragma unroll
        for (int s = 0; s < 7; s++)
            g_aF[rb + s * ZDIM + z] = __float2half_rn(f[s]);
    }
}

__global__ void final_out(const float* __restrict__ p3_w, const float* __restrict__ p3_b,
                          float* __restrict__ out) {
    const int warp = (blockIdx.x * blockDim.x + threadIdx.x) >> 5;
    const int lane = threadIdx.x & 31;
    if (warp >= BSZ) return;
    const float* h = g_h2 + (size_t)warp * H2D;
    float s = 0.f;
    for (int j = lane; j < H2D; j += 32) s += h[j] * p3_w[j];
#pragma unroll
    for (int off = 16; off; off >>= 1) s += __shfl_xor_sync(0xffffffffu, s, off);
    if (lane == 0) out[warp] = 1.f / (1.f + expf(-(s + p3_b[0])));
}

// ---------------- host launcher ----------------
extern "C" void kernel_launch(void* const* d_in, const int* in_sizes, int n_in,
                              void* d_out, int out_size) {
    const float* vis   = (const float*)d_in[0];
    const float* txt   = (const float*)d_in[1];
    const float* sim   = (const float*)d_in[2];
    const float* rvis  = (const float*)d_in[3];
    const float* rtxt  = (const float*)d_in[4];
    const float* rlbl  = (const float*)d_in[5];
    const float* usr   = (const float*)d_in[6];
    const float* rusr  = (const float*)d_in[7];
    const float* vis_w = (const float*)d_in[9],  *vis_b = (const float*)d_in[10];
    const float* txt_w = (const float*)d_in[11], *txt_b = (const float*)d_in[12];
    const float* usr_w = (const float*)d_in[13], *usr_b = (const float*)d_in[14];
    const float* rvis_w = (const float*)d_in[15], *rvis_b = (const float*)d_in[16];
    const float* rtxt_w = (const float*)d_in[17], *rtxt_b = (const float*)d_in[18];
    const float* rusr_w = (const float*)d_in[19], *rusr_b = (const float*)d_in[20];
    const float* hg_w  = (const float*)d_in[21], *hg_b = (const float*)d_in[22];
    const float* lbl_w = (const float*)d_in[23], *lbl_b = (const float*)d_in[24];
    const float* p1_w  = (const float*)d_in[25], *p1_b = (const float*)d_in[26];
    const float* p2_w  = (const float*)d_in[27], *p2_b = (const float*)d_in[28];
    const float* p3_w  = (const float*)d_in[29], *p3_b = (const float*)d_in[30];

    float *Y, *h2, *biasD;
    __half *aS, *aR, *wE, *aM, *wHg, *aF, *wP1, *aH1, *wP2;
    cudaGetSymbolAddress((void**)&Y, g_Y);
    cudaGetSymbolAddress((void**)&h2, g_h2);
    cudaGetSymbolAddress((void**)&biasD, g_bias);
    cudaGetSymbolAddress((void**)&aS, g_aS);
    cudaGetSymbolAddress((void**)&aR, g_aR);
    cudaGetSymbolAddress((void**)&wE, g_wE);
    cudaGetSymbolAddress((void**)&aM, g_aM);
    cudaGetSymbolAddress((void**)&wHg, g_wHg);
    cudaGetSymbolAddress((void**)&aF, g_aF);
    cudaGetSymbolAddress((void**)&wP1, g_wP1);
    cudaGetSymbolAddress((void**)&aH1, g_aH1);
    cudaGetSymbolAddress((void**)&wP2, g_wP2);

    cudaFuncSetAttribute(hgemm<1,1,1>, cudaFuncAttributeMaxDynamicSharedMemorySize, SMEM_BYTES);
    cudaFuncSetAttribute(hgemm<0,0,0>, cudaFuncAttributeMaxDynamicSharedMemorySize, SMEM_BYTES);
    cudaFuncSetAttribute(hgemm<2,1,0>, cudaFuncAttributeMaxDynamicSharedMemorySize, SMEM_BYTES);
    cudaFuncSetAttribute(hgemm<2,0,0>, cudaFuncAttributeMaxDynamicSharedMemorySize, SMEM_BYTES);

    const size_t aSz = (size_t)BSZ * FDIM, aRz = (size_t)NRET * FDIM;
    const size_t wEz = (size_t)512 * FDIM;

    // ---- ONE conv launch for everything ----
    {
        ConvTable T; T.n = 15;
        T.j[0] = {txt_w,  wE + 0 * wEz, PDIM, FDIM, 512, FDIM};
        T.j[1] = {vis_w,  wE + 1 * wEz, PDIM, FDIM, 512, FDIM};
        T.j[2] = {usr_w,  wE + 2 * wEz, PDIM, FDIM, 512, FDIM};
        T.j[3] = {rtxt_w, wE + 3 * wEz, PDIM, FDIM, 512, FDIM};
        T.j[4] = {rvis_w, wE + 4 * wEz, PDIM, FDIM, 512, FDIM};
        T.j[5] = {rusr_w, wE + 5 * wEz, PDIM, FDIM, 512, FDIM};
        T.j[6] = {hg_w, wHg, ZDIM, PDIM, 512, KP_HG};
        T.j[7] = {p1_w, wP1, H1D, FEATD, 1024, KP_P1};
        T.j[8] = {p2_w, wP2, H2D, H1D, 256, KP_P2};
        T.j[9]  = {txt, aS + 0 * aSz, BSZ, FDIM, BSZ, FDIM};
        T.j[10] = {vis, aS + 1 * aSz, BSZ, FDIM, BSZ, FDIM};
        T.j[11] = {usr, aS + 2 * aSz, BSZ, FDIM, BSZ, FDIM};
        T.j[12] = {rtxt, aR + 0 * aRz, NRET, FDIM, NRET, FDIM};
        T.j[13] = {rvis, aR + 1 * aRz, NRET, FDIM, NRET, FDIM};
        T.j[14] = {rusr, aR + 2 * aRz, NRET, FDIM, NRET, FDIM};
        long long total = 0;
        for (int i = 0; i < T.n; i++) {
            T.nG[i] = (long long)T.j[i].rp * (T.j[i].cp >> 3);
            total += T.nG[i];
        }
        conv_batch<<<(unsigned)((total + 255) / 256), 256>>>(T, total);
    }

    bias_pack<<<1, 1024>>>(txt_b, vis_b, usr_b, rtxt_b, rvis_b, rusr_b, hg_b, p1_b, p2_b);

    // ---- 1) ALL 6 embeddings, ONE launch (z=0..5, singles early-exit y>=32) ----
    hgemm<1,1,1><<<dim3(2, 320, 6), 512, SMEM_BYTES>>>(
        nullptr, 0, nullptr, 0, nullptr, 0, nullptr, 0, 0, 0, 0, 0);

    // ---- 2) means (+pair means) -> g_aM plane ----
    build_means_fused<<<(BSZ * (PDIM / 4) + 255) / 256, 256>>>();

    // ---- 3) hg projection -> g_Y fp32 ----
    hgemm<0,0,0><<<dim3(2, 129, 1), 512, SMEM_BYTES>>>(
        aM, 0, wHg, 0,
        biasD + 3072, 0, Y, 0, ZDIM, M_ROWS, ZDIM, KP_HG);

    // ---- 4) feature assembly -> g_aF plane ----
    build_feat<<<BSZ, 256>>>(sim, rlbl, lbl_w, lbl_b);

    // ---- 5) MLP head ----
    hgemm<2,1,0><<<dim3(4, 32, 1), 512, SMEM_BYTES>>>(
        aF, 0, wP1, 0,
        biasD + 3584, 0, aH1, 0, KP_P2, BSZ, H1D, KP_P1);
    hgemm<2,0,0><<<dim3(1, 32, 1), 512, SMEM_BYTES>>>(
        aH1, 0, wP2, 0,
        biasD + 4608, 0, h2, 0, H2D, BSZ, H2D, KP_P2);

    final_out<<<(BSZ * 32 + 255) / 256, 256>>>(p3_w, p3_b, (float*)d_out);
}